// round 8
// baseline (speedup 1.0000x reference)
#include <cuda_runtime.h>
#include <cstdint>

#define NND 16384
#define NE  262144
#define HID 128
#define BATCH 128
#define SEQ 128
#define NL 4
#define WSZ (HID*HID)

// smem word offsets (single-stage, fold-in-registers)
#define AOFF 0      // A: 128 x 36
#define WOFF 4608   // W: 32 x 72
#define OPWORDS 6912
#define IDXOFF 8704

// ---------------- scratch ----------------
__device__ float g_h[NND * HID];
__device__ float g_eA[NE * HID];
__device__ float g_eB[NE * HID];
__device__ float g_eijA[NE * HID];
__device__ float g_eijB[NE * HID];
__device__ float g_Ax[NND * HID];
__device__ float g_Bx[NND * HID];
__device__ float g_Dx[NND * HID];
__device__ float g_Ex[NND * HID];
__device__ float g_num[NND * HID];
__device__ float g_den[NND * HID];
__device__ float g_part[2048 * 256];
__device__ float g_scN[HID], g_shN[HID], g_scE[HID], g_shE[HID];
__device__ float g_pool[BATCH * HID];
__device__ float g_t1[BATCH * 64];
__device__ float g_t2[BATCH * 32];
// edge sort
__device__ int g_cnt[NND];
__device__ int g_src2[NE];
__device__ int g_dst2[NE];
__device__ int g_perm[NE];

__device__ __forceinline__ unsigned f2tf(float f) {
    unsigned u; asm("cvt.rna.tf32.f32 %0, %1;" : "=r"(u) : "f"(f)); return u;
}
__device__ __forceinline__ void splitv(float f, unsigned& hi, unsigned& lo) {
    hi = f2tf(f);
    lo = f2tf(f - __uint_as_float(hi));
}
__device__ __forceinline__ void mma8(float* d, const unsigned* a, const unsigned* b) {
    asm volatile("mma.sync.aligned.m16n8k8.row.col.f32.tf32.tf32.f32 "
        "{%0,%1,%2,%3}, {%4,%5,%6,%7}, {%8,%9}, {%0,%1,%2,%3};"
        : "+f"(d[0]), "+f"(d[1]), "+f"(d[2]), "+f"(d[3])
        : "r"(a[0]), "r"(a[1]), "r"(a[2]), "r"(a[3]), "r"(b[0]), "r"(b[1]));
}
__device__ __forceinline__ void red4(float* p, float4 v) {
    asm volatile("red.global.add.v4.f32 [%0], {%1,%2,%3,%4};"
        :: "l"(p), "f"(v.x), "f"(v.y), "f"(v.z), "f"(v.w) : "memory");
}

// ---------------- init: zero num/den/part/cnt ----------------
__global__ void init_kernel() {
    int i = blockIdx.x * 256 + threadIdx.x;
    float4 z = make_float4(0.f, 0.f, 0.f, 0.f);
    if (i < NND * HID / 4) { ((float4*)g_num)[i] = z; ((float4*)g_den)[i] = z; }
    if (i < 2048 * 64) ((float4*)g_part)[i] = z;
    if (i < NND / 4) ((int4*)g_cnt)[i] = make_int4(0, 0, 0, 0);
}
__global__ void zero_nd_kernel() {
    int i = blockIdx.x * 256 + threadIdx.x;
    float4 z = make_float4(0.f, 0.f, 0.f, 0.f);
    if (i < NND * HID / 4) { ((float4*)g_num)[i] = z; ((float4*)g_den)[i] = z; }
    if (i < 2048 * 64) ((float4*)g_part)[i] = z;
}

// ---------------- edge counting sort ----------------
__global__ void hist_kernel(const int* __restrict__ dst) {
    int i = blockIdx.x * blockDim.x + threadIdx.x;
    if (i < NE) atomicAdd(&g_cnt[dst[i]], 1);
}
__global__ __launch_bounds__(1024) void scan_kernel() {
    __shared__ int ssum[1024];
    int tid = threadIdx.x;
    int base = tid * 16;
    int loc[16]; int s = 0;
#pragma unroll
    for (int i = 0; i < 16; i++) { loc[i] = s; s += g_cnt[base + i]; }
    ssum[tid] = s;
    __syncthreads();
    for (int off = 1; off < 1024; off <<= 1) {
        int v = (tid >= off) ? ssum[tid - off] : 0;
        __syncthreads();
        ssum[tid] += v;
        __syncthreads();
    }
    int pre = (tid == 0) ? 0 : ssum[tid - 1];
#pragma unroll
    for (int i = 0; i < 16; i++) g_cnt[base + i] = pre + loc[i];
}
__global__ void scatter_kernel(const int* __restrict__ src, const int* __restrict__ dst) {
    int i = blockIdx.x * blockDim.x + threadIdx.x;
    if (i >= NE) return;
    int d = dst[i];
    int pos = atomicAdd(&g_cnt[d], 1);
    g_perm[pos] = i;
    g_src2[pos] = src[i];
    g_dst2[pos] = d;
}

// ---------------- input projection ----------------
__global__ void input_proj_kernel(const float* __restrict__ x, const float* __restrict__ pe,
                                  const float* __restrict__ nw, const float* __restrict__ nb,
                                  const float* __restrict__ pw, const float* __restrict__ pb) {
    int row = blockIdx.x;
    int c = threadIdx.x;
    __shared__ float xs[64];
    __shared__ float ps[16];
    if (c < 64) xs[c] = x[row * 64 + c];
    else if (c < 80) ps[c - 64] = pe[row * 16 + (c - 64)];
    __syncthreads();
    float acc;
    if (c < 112) {
        acc = nb[c];
#pragma unroll
        for (int k = 0; k < 64; k++) acc += xs[k] * nw[k * 112 + c];
    } else {
        int cc = c - 112;
        acc = pb[cc];
#pragma unroll
        for (int k = 0; k < 16; k++) acc += ps[k] * pw[k * 16 + cc];
    }
    g_h[row * HID + c] = acc;
}

// ================= 3xTF32 GEMM, tile 128x64 (N split via blockIdx.z), multi-W via blockIdx.y ==
__global__ __launch_bounds__(256, 3) void gemm_tc(
    const float* __restrict__ A, const float* __restrict__ foldE, int doFold,
    const float* __restrict__ W0, const float* __restrict__ W1,
    const float* __restrict__ W2, const float* __restrict__ W3,
    const float* __restrict__ b0, const float* __restrict__ b1,
    const float* __restrict__ b2, const float* __restrict__ b3,
    float* __restrict__ C0, float* __restrict__ C1,
    float* __restrict__ C2, float* __restrict__ C3) {
    int y = blockIdx.y, z = blockIdx.z;
    const float* W = (y == 0) ? W0 : (y == 1) ? W1 : (y == 2) ? W2 : W3;
    const float* bb = (y == 0) ? b0 : (y == 1) ? b1 : (y == 2) ? b2 : b3;
    float* C = (y == 0) ? C0 : (y == 1) ? C1 : (y == 2) ? C2 : C3;

    extern __shared__ float smf[];
    float* As = smf + AOFF;
    float* Ws = smf + WOFF;
    int tid = threadIdx.x, lane = tid & 31, wid = tid >> 5;
    int wm = wid & 3, wn = wid >> 2, g = lane >> 2, t = lane & 3;
    int r0 = blockIdx.x * 128;
    int arow = tid >> 1, acb = (tid & 1) * 16;
    int wrow = tid >> 3, wcb = (tid & 7) * 8;

    float acc[2][4][4];
#pragma unroll
    for (int i = 0; i < 2; i++)
#pragma unroll
        for (int j = 0; j < 4; j++)
#pragma unroll
            for (int q = 0; q < 4; q++) acc[i][j][q] = 0.f;

    for (int k0 = 0; k0 < 128; k0 += 32) {
        __syncthreads();
#pragma unroll
        for (int q = 0; q < 4; q++) {
            int kc = acb + q * 4;
            float4 av = *(const float4*)&A[(size_t)(r0 + arow) * HID + k0 + kc];
            if (doFold) {
                float4 ev = *(const float4*)&foldE[(size_t)(r0 + arow) * HID + k0 + kc];
                float4 sc = *(const float4*)&g_scN[k0 + kc];
                float4 sh = *(const float4*)&g_shN[k0 + kc];
                av.x = fmaxf(av.x * sc.x + sh.x, 0.f) + ev.x;
                av.y = fmaxf(av.y * sc.y + sh.y, 0.f) + ev.y;
                av.z = fmaxf(av.z * sc.z + sh.z, 0.f) + ev.z;
                av.w = fmaxf(av.w * sc.w + sh.w, 0.f) + ev.w;
            }
            *(float4*)&As[arow * 36 + kc] = av;
        }
#pragma unroll
        for (int q = 0; q < 2; q++)
            *(float4*)&Ws[wrow * 72 + wcb + q * 4] =
                *(const float4*)&W[(size_t)(k0 + wrow) * HID + z * 64 + wcb + q * 4];
        __syncthreads();
#pragma unroll
        for (int kk = 0; kk < 32; kk += 8) {
            unsigned ah[2][4], al[2][4];
#pragma unroll
            for (int mt = 0; mt < 2; mt++) {
                int rb = wm * 32 + mt * 16 + g;
                splitv(As[rb * 36 + kk + t],           ah[mt][0], al[mt][0]);
                splitv(As[(rb + 8) * 36 + kk + t],     ah[mt][1], al[mt][1]);
                splitv(As[rb * 36 + kk + t + 4],       ah[mt][2], al[mt][2]);
                splitv(As[(rb + 8) * 36 + kk + t + 4], ah[mt][3], al[mt][3]);
            }
#pragma unroll
            for (int nt = 0; nt < 4; nt++) {
                int cb = wn * 32 + nt * 8 + g;
                unsigned bh[2], bl[2];
                splitv(Ws[(kk + t) * 72 + cb],     bh[0], bl[0]);
                splitv(Ws[(kk + t + 4) * 72 + cb], bh[1], bl[1]);
#pragma unroll
                for (int mt = 0; mt < 2; mt++) {
                    mma8(acc[mt][nt], ah[mt], bh);
                    mma8(acc[mt][nt], al[mt], bh);
                    mma8(acc[mt][nt], ah[mt], bl);
                }
            }
        }
    }
#pragma unroll
    for (int mt = 0; mt < 2; mt++) {
#pragma unroll
        for (int nt = 0; nt < 4; nt++) {
            int c = z * 64 + wn * 32 + nt * 8 + 2 * t;
            float bx = bb[c], by = bb[c + 1];
            int r = r0 + wm * 32 + mt * 16 + g;
            *(float2*)&C[(size_t)r * HID + c] = make_float2(acc[mt][nt][0] + bx, acc[mt][nt][1] + by);
            *(float2*)&C[(size_t)(r + 8) * HID + c] = make_float2(acc[mt][nt][2] + bx, acc[mt][nt][3] + by);
        }
    }
}

// ================= edge GEMM (sorted), tile 128x64: fold loader + segment-reduce epilogue ====
// NOTE: A/C and foldE/foldOut are DISTINCT buffers (ping-pong) — no in-place aliasing.
__global__ __launch_bounds__(256, 3) void gemm_tc_edge(
    const float* __restrict__ A, const float* __restrict__ foldE, float* __restrict__ foldOut,
    const float* __restrict__ W, const float* __restrict__ bias,
    float* __restrict__ C,
    const float* __restrict__ Dx, const float* __restrict__ Ex, const float* __restrict__ Bx,
    int doStats, int permA, int permF, int writeC, int writeFold) {
    extern __shared__ float smf[];
    float* As = smf + AOFF;
    float* Ws = smf + WOFF;
    float* tile = smf;                 // overlay 128 x 68 after mainloop
    int* sidx = (int*)(smf + IDXOFF);
    int* didx = sidx + 128;
    int* pidx = didx + 128;

    int tid = threadIdx.x, lane = tid & 31, wid = tid >> 5;
    int wm = wid & 3, wn = wid >> 2, g = lane >> 2, t = lane & 3;
    int r0 = blockIdx.x * 128;
    int z = blockIdx.z;
    int arow = tid >> 1, acb = (tid & 1) * 16;
    int wrow = tid >> 3, wcb = (tid & 7) * 8;

    if (tid < 128) {
        sidx[tid] = g_src2[r0 + tid];
        didx[tid] = g_dst2[r0 + tid];
        pidx[tid] = g_perm[r0 + tid];
    }
    __syncthreads();

    float acc[2][4][4];
#pragma unroll
    for (int i = 0; i < 2; i++)
#pragma unroll
        for (int j = 0; j < 4; j++)
#pragma unroll
            for (int q = 0; q < 4; q++) acc[i][j][q] = 0.f;

    int doFold = (foldE != nullptr);
    int aIdx = permA ? pidx[arow] : (r0 + arow);
    int fIdx = permF ? pidx[arow] : (r0 + arow);
    int wF = writeFold && (z == 0);

    for (int k0 = 0; k0 < 128; k0 += 32) {
        __syncthreads();
#pragma unroll
        for (int q = 0; q < 4; q++) {
            int kc = acb + q * 4;
            float4 av = *(const float4*)&A[(size_t)aIdx * HID + k0 + kc];
            if (doFold) {
                float4 ev = *(const float4*)&foldE[(size_t)fIdx * HID + k0 + kc];
                float4 sc = *(const float4*)&g_scE[k0 + kc];
                float4 sh = *(const float4*)&g_shE[k0 + kc];
                av.x = fmaxf(av.x * sc.x + sh.x, 0.f) + ev.x;
                av.y = fmaxf(av.y * sc.y + sh.y, 0.f) + ev.y;
                av.z = fmaxf(av.z * sc.z + sh.z, 0.f) + ev.z;
                av.w = fmaxf(av.w * sc.w + sh.w, 0.f) + ev.w;
                if (wF) *(float4*)&foldOut[(size_t)(r0 + arow) * HID + k0 + kc] = av;
            }
            *(float4*)&As[arow * 36 + kc] = av;
        }
#pragma unroll
        for (int q = 0; q < 2; q++)
            *(float4*)&Ws[wrow * 72 + wcb + q * 4] =
                *(const float4*)&W[(size_t)(k0 + wrow) * HID + z * 64 + wcb + q * 4];
        __syncthreads();
#pragma unroll
        for (int kk = 0; kk < 32; kk += 8) {
            unsigned ah[2][4], al[2][4];
#pragma unroll
            for (int mt = 0; mt < 2; mt++) {
                int rb = wm * 32 + mt * 16 + g;
                splitv(As[rb * 36 + kk + t],           ah[mt][0], al[mt][0]);
                splitv(As[(rb + 8) * 36 + kk + t],     ah[mt][1], al[mt][1]);
                splitv(As[rb * 36 + kk + t + 4],       ah[mt][2], al[mt][2]);
                splitv(As[(rb + 8) * 36 + kk + t + 4], ah[mt][3], al[mt][3]);
            }
#pragma unroll
            for (int nt = 0; nt < 4; nt++) {
                int cb = wn * 32 + nt * 8 + g;
                unsigned bh[2], bl[2];
                splitv(Ws[(kk + t) * 72 + cb],     bh[0], bl[0]);
                splitv(Ws[(kk + t + 4) * 72 + cb], bh[1], bl[1]);
#pragma unroll
                for (int mt = 0; mt < 2; mt++) {
                    mma8(acc[mt][nt], ah[mt], bh);
                    mma8(acc[mt][nt], al[mt], bh);
                    mma8(acc[mt][nt], ah[mt], bl);
                }
            }
        }
    }
    __syncthreads();
    // stage accumulators to smem tile (overlays operand region)
#pragma unroll
    for (int mt = 0; mt < 2; mt++) {
#pragma unroll
        for (int nt = 0; nt < 4; nt++) {
            int cc = wn * 32 + nt * 8 + 2 * t;
            int r = wm * 32 + mt * 16 + g;
            tile[r * 68 + cc] = acc[mt][nt][0];
            tile[r * 68 + cc + 1] = acc[mt][nt][1];
            tile[(r + 8) * 68 + cc] = acc[mt][nt][2];
            tile[(r + 8) * 68 + cc + 1] = acc[mt][nt][3];
        }
    }
    __syncthreads();
    // epilogue: 16 threads x 4ch per row-group of 8 sorted rows; segment-reduce on dst runs
    {
        int c4l = (tid & 15) * 4;
        int c4g = z * 64 + c4l;
        int chunk = tid >> 4;  // 0..15, 8 rows each
        float4 bcv = *(const float4*)&bias[c4g];
        float4 s1v = make_float4(0.f, 0.f, 0.f, 0.f);
        float4 s2v = make_float4(0.f, 0.f, 0.f, 0.f);
        float4 accN = make_float4(0.f, 0.f, 0.f, 0.f);
        float4 accD = make_float4(0.f, 0.f, 0.f, 0.f);
        int curd = didx[chunk * 8];
#pragma unroll
        for (int rr = 0; rr < 8; rr++) {
            int r = chunk * 8 + rr;
            int d = didx[r], s = sidx[r];
            if (d != curd) {
                red4(&g_num[(size_t)curd * HID + c4g], accN);
                red4(&g_den[(size_t)curd * HID + c4g], accD);
                accN = make_float4(0.f, 0.f, 0.f, 0.f);
                accD = make_float4(0.f, 0.f, 0.f, 0.f);
                curd = d;
            }
            float4 tv = *(float4*)&tile[r * 68 + c4l];
            float4 dx = *(const float4*)&Dx[(size_t)d * HID + c4g];
            float4 ex = *(const float4*)&Ex[(size_t)s * HID + c4g];
            float4 bx = *(const float4*)&Bx[(size_t)s * HID + c4g];
            float4 v;
            v.x = tv.x + bcv.x + dx.x + ex.x;
            v.y = tv.y + bcv.y + dx.y + ex.y;
            v.z = tv.z + bcv.z + dx.z + ex.z;
            v.w = tv.w + bcv.w + dx.w + ex.w;
            if (writeC) *(float4*)&C[(size_t)(r0 + r) * HID + c4g] = v;
            float4 sg;
            sg.x = 1.f / (1.f + __expf(-v.x));
            sg.y = 1.f / (1.f + __expf(-v.y));
            sg.z = 1.f / (1.f + __expf(-v.z));
            sg.w = 1.f / (1.f + __expf(-v.w));
            accN.x += sg.x * bx.x; accN.y += sg.y * bx.y;
            accN.z += sg.z * bx.z; accN.w += sg.w * bx.w;
            accD.x += sg.x; accD.y += sg.y; accD.z += sg.z; accD.w += sg.w;
            s1v.x += v.x; s1v.y += v.y; s1v.z += v.z; s1v.w += v.w;
            s2v.x += v.x * v.x; s2v.y += v.y * v.y; s2v.z += v.z * v.z; s2v.w += v.w * v.w;
        }
        red4(&g_num[(size_t)curd * HID + c4g], accN);
        red4(&g_den[(size_t)curd * HID + c4g], accD);
        if (doStats) {
            red4(&g_part[blockIdx.x * 256 + c4g], s1v);
            red4(&g_part[blockIdx.x * 256 + 128 + c4g], s2v);
        }
    }
}

// ---------------- h_new = Ax + num/(den+eps) fused with BN partials ----------------
__global__ void node_hnew_stats_kernel() {
    int c = threadIdx.x;
    float s = 0.f, ss = 0.f;
    for (int r = blockIdx.x; r < NND; r += gridDim.x) {
        int i = r * HID + c;
        float v = g_Ax[i] + g_num[i] / (g_den[i] + 1e-6f);
        g_Ax[i] = v;
        s += v; ss += v * v;
    }
    g_part[blockIdx.x * 256 + c] = s;
    g_part[blockIdx.x * 256 + 128 + c] = ss;
}

// ---------------- BN finalize ----------------
__global__ void bn_finalize2(int G, float invM, const float* __restrict__ gamma,
                             const float* __restrict__ beta,
                             float* __restrict__ scale, float* __restrict__ shift) {
    int c = blockIdx.x;
    int tid = threadIdx.x;
    double s = 0.0, ss = 0.0;
    for (int gi = tid; gi < G; gi += 256) {
        s  += (double)g_part[gi * 256 + c];
        ss += (double)g_part[gi * 256 + 128 + c];
    }
    __shared__ double rs[256], rss[256];
    rs[tid] = s; rss[tid] = ss;
    __syncthreads();
    for (int o = 128; o > 0; o >>= 1) {
        if (tid < o) { rs[tid] += rs[tid + o]; rss[tid] += rss[tid + o]; }
        __syncthreads();
    }
    if (tid == 0) {
        double mu = rs[0] * (double)invM;
        double var = rss[0] * (double)invM - mu * mu;
        float inv = rsqrtf((float)var + 1e-5f);
        float scv = gamma[c] * inv;
        scale[c] = scv;
        shift[c] = beta[c] - (float)mu * scv;
    }
}

// ---------------- dense attention per (head, batch graph) ----------------
__global__ void attn_kernel(const float* __restrict__ q, const float* __restrict__ k,
                            const float* __restrict__ v, const float* __restrict__ sph,
                            float* __restrict__ o) {
    extern __shared__ float smf[];
    float* ks = smf;
    float* vs = smf + 128 * 36;
    float* ps = smf + 2 * 128 * 36;
    int head = blockIdx.x, b = blockIdx.y;
    int s = threadIdx.x;
    int nodebase = (b * SEQ + s) * HID + head * 32;
    float qr[32];
#pragma unroll
    for (int d4 = 0; d4 < 8; d4++) {
        float4 tq = *(const float4*)&q[nodebase + d4 * 4];
        qr[d4 * 4] = tq.x; qr[d4 * 4 + 1] = tq.y; qr[d4 * 4 + 2] = tq.z; qr[d4 * 4 + 3] = tq.w;
        *(float4*)&ks[s * 36 + d4 * 4] = *(const float4*)&k[nodebase + d4 * 4];
        *(float4*)&vs[s * 36 + d4 * 4] = *(const float4*)&v[nodebase + d4 * 4];
    }
    __syncthreads();
    const float isd = 0.17677669529663687f;
    for (int t = 0; t < SEQ; t++) {
        float acc = 0.f;
#pragma unroll
        for (int d4 = 0; d4 < 8; d4++) {
            float4 kk = *(float4*)&ks[t * 36 + d4 * 4];
            acc += qr[d4 * 4] * kk.x + qr[d4 * 4 + 1] * kk.y +
                   qr[d4 * 4 + 2] * kk.z + qr[d4 * 4 + 3] * kk.w;
        }
        ps[s * 133 + t] = acc * isd;
    }
    __syncthreads();
    const float* sb = sph + b * SEQ * SEQ;
    for (int i = s; i < SEQ * SEQ; i += 128) {
        int s2 = i >> 7, t2 = i & 127;
        ps[s2 * 133 + t2] *= sb[i];
    }
    __syncthreads();
    float mx = -1e30f;
    for (int t = 0; t < SEQ; t++) mx = fmaxf(mx, ps[s * 133 + t]);
    float sum = 0.f;
    for (int t = 0; t < SEQ; t++) {
        float e = __expf(ps[s * 133 + t] - mx);
        ps[s * 133 + t] = e;
        sum += e;
    }
    float inv = 1.f / sum;
    float acc[32];
#pragma unroll
    for (int d = 0; d < 32; d++) acc[d] = 0.f;
    for (int t = 0; t < SEQ; t++) {
        float p = ps[s * 133 + t] * inv;
#pragma unroll
        for (int d4 = 0; d4 < 8; d4++) {
            float4 vvv = *(float4*)&vs[t * 36 + d4 * 4];
            acc[d4 * 4] += p * vvv.x; acc[d4 * 4 + 1] += p * vvv.y;
            acc[d4 * 4 + 2] += p * vvv.z; acc[d4 * 4 + 3] += p * vvv.w;
        }
    }
#pragma unroll
    for (int d4 = 0; d4 < 8; d4++) {
        float4 t4 = make_float4(acc[d4 * 4], acc[d4 * 4 + 1], acc[d4 * 4 + 2], acc[d4 * 4 + 3]);
        *(float4*)&o[nodebase + d4 * 4] = t4;
    }
}

// ---------------- mean pool + tiny MLP ----------------
__global__ void pool_kernel() {
    int b = blockIdx.x, c = threadIdx.x;
    float s = 0.f;
    for (int i = 0; i < SEQ; i++) s += g_h[(b * SEQ + i) * HID + c];
    g_pool[b * HID + c] = s * (1.f / 128.f);
}
__global__ void mlp_kernel(const float* __restrict__ in, const float* __restrict__ W,
                           const float* __restrict__ bias, float* __restrict__ out,
                           int K, int Ncol, int doRelu) {
    int r = blockIdx.x;
    __shared__ float xs[128];
    if ((int)threadIdx.x < K) xs[threadIdx.x] = in[r * K + threadIdx.x];
    __syncthreads();
    int c = threadIdx.x;
    if (c < Ncol) {
        float acc = bias[c];
        for (int k = 0; k < K; k++) acc += xs[k] * W[k * Ncol + c];
        if (doRelu) acc = fmaxf(acc, 0.f);
        out[r * Ncol + c] = acc;
    }
}

// ---------------- launch ----------------
extern "C" void kernel_launch(void* const* d_in, const int* in_sizes, int n_in,
                              void* d_out, int out_size) {
    const float* x        = (const float*)d_in[0];
    const float* pe       = (const float*)d_in[1];
    const float* edge_attr= (const float*)d_in[2];
    const float* sph      = (const float*)d_in[3];
    const float* node_w   = (const float*)d_in[4];
    const float* node_b   = (const float*)d_in[5];
    const float* pe_w     = (const float*)d_in[6];
    const float* pe_b     = (const float*)d_in[7];
    const float* Aw       = (const float*)d_in[8];
    const float* Ab       = (const float*)d_in[9];
    const float* Bw       = (const float*)d_in[10];
    const float* Bb       = (const float*)d_in[11];
    const float* Cw       = (const float*)d_in[12];
    const float* Cb       = (const float*)d_in[13];
    const float* Dw       = (const float*)d_in[14];
    const float* Db       = (const float*)d_in[15];
    const float* Ew       = (const float*)d_in[16];
    const float* Eb       = (const float*)d_in[17];
    const float* bnxg     = (const float*)d_in[18];
    const float* bnxb     = (const float*)d_in[19];
    const float* bneg     = (const float*)d_in[20];
    const float* bneb     = (const float*)d_in[21];
    const float* attw     = (const float*)d_in[22];
    const float* attb     = (const float*)d_in[23];
    const float* m1w      = (const float*)d_in[24];
    const float* m1b      = (const float*)d_in[25];
    const float* m2w      = (const float*)d_in[26];
    const float* m2b      = (const float*)d_in[27];
    const float* m3w      = (const float*)d_in[28];
    const float* m3b      = (const float*)d_in[29];
    const int*   ei       = (const int*)d_in[30];
    float* out = (float*)d_out;

    float *p_h, *p_eA, *p_eB, *p_eijA, *p_eijB, *p_Ax, *p_Bx, *p_Dx, *p_Ex, *p_num, *p_den;
    float *p_scN, *p_shN, *p_scE, *p_shE, *p_pool, *p_t1, *p_t2;
    cudaGetSymbolAddress((void**)&p_h,    g_h);
    cudaGetSymbolAddress((void**)&p_eA,   g_eA);
    cudaGetSymbolAddress((void**)&p_eB,   g_eB);
    cudaGetSymbolAddress((void**)&p_eijA, g_eijA);
    cudaGetSymbolAddress((void**)&p_eijB, g_eijB);
    cudaGetSymbolAddress((void**)&p_Ax,   g_Ax);
    cudaGetSymbolAddress((void**)&p_Bx,   g_Bx);
    cudaGetSymbolAddress((void**)&p_Dx,   g_Dx);
    cudaGetSymbolAddress((void**)&p_Ex,   g_Ex);
    cudaGetSymbolAddress((void**)&p_num,  g_num);
    cudaGetSymbolAddress((void**)&p_den,  g_den);
    cudaGetSymbolAddress((void**)&p_scN,  g_scN);
    cudaGetSymbolAddress((void**)&p_shN,  g_shN);
    cudaGetSymbolAddress((void**)&p_scE,  g_scE);
    cudaGetSymbolAddress((void**)&p_shE,  g_shE);
    cudaGetSymbolAddress((void**)&p_pool, g_pool);
    cudaGetSymbolAddress((void**)&p_t1,   g_t1);
    cudaGetSymbolAddress((void**)&p_t2,   g_t2);

    float* eij_bufs[2] = { p_eijA, p_eijB };
    float* e_bufs[2]   = { p_eA, p_eB };

    const int* src = ei;
    const int* dst = ei + NE;
    const int ATTN_SMEM = (2 * 128 * 36 + 128 * 133) * 4;
    const int PLAIN_SMEM = OPWORDS * 4;                 // 27648
    const int EDGE_SMEM = (IDXOFF + 384) * 4;           // 36352
    cudaFuncSetAttribute(attn_kernel, cudaFuncAttributeMaxDynamicSharedMemorySize, ATTN_SMEM);
    cudaFuncSetAttribute(gemm_tc, cudaFuncAttributeMaxDynamicSharedMemorySize, PLAIN_SMEM);
    cudaFuncSetAttribute(gemm_tc_edge, cudaFuncAttributeMaxDynamicSharedMemorySize, EDGE_SMEM);

    // 1: init (zeros num/den/part/cnt)   2-4: edge counting sort   5: input proj
    init_kernel<<<2048, 256>>>();
    hist_kernel<<<NE / 256, 256>>>(dst);
    scan_kernel<<<1, 1024>>>();
    scatter_kernel<<<NE / 256, 256>>>(src, dst);
    input_proj_kernel<<<NND, 128>>>(x, pe, node_w, node_b, pe_w, pe_b);

    for (int l = 0; l < NL; l++) {
        if (l > 0) zero_nd_kernel<<<2048, 256>>>();
        // 6th launch overall (l==0): A,B,D,E projections — profiled by ncu
        dim3 g4(NND / 128, 4, 2);
        gemm_tc<<<g4, 256, PLAIN_SMEM>>>(p_h, nullptr, 0,
            Aw + l * WSZ, Bw + l * WSZ, Dw + l * WSZ, Ew + l * WSZ,
            Ab + l * HID, Bb + l * HID, Db + l * HID, Eb + l * HID,
            p_Ax, p_Bx, p_Dx, p_Ex);
        // ping-pong: read eij written by layer l-1, write buffer l&1 (no aliasing)
        const float* eA    = (l == 0) ? edge_attr : eij_bufs[(l - 1) & 1];
        float* eij_out     = eij_bufs[l & 1];
        const float* foldE = (l == 0) ? nullptr : ((l == 1) ? edge_attr : e_bufs[(l - 1) & 1]);
        float* fold_out    = e_bufs[l & 1];
        int permA = (l == 0) ? 1 : 0;
        int permF = (l == 1) ? 1 : 0;
        int last = (l == NL - 1);
        dim3 ge(NE / 128, 1, 2);
        gemm_tc_edge<<<ge, 256, EDGE_SMEM>>>(
            eA, foldE, fold_out, Cw + l * WSZ, Cb + l * HID, eij_out,
            p_Dx, p_Ex, p_Bx, last ? 0 : 1, permA, permF,
            last ? 0 : 1, last ? 0 : 1);
        if (!last)
            bn_finalize2<<<HID, 256>>>(2048, 1.f / NE, bneg + l * HID, bneb + l * HID, p_scE, p_shE);
        node_hnew_stats_kernel<<<1024, 128>>>();
        bn_finalize2<<<HID, 256>>>(1024, 1.f / NND, bnxg + l * HID, bnxb + l * HID, p_scN, p_shN);
        // q,k,v projections with fused node BN fold (h' never materialized)
        dim3 g3(NND / 128, 3, 2);
        gemm_tc<<<g3, 256, PLAIN_SMEM>>>(p_Ax, p_h, 1,
            attw + 0 * WSZ, attw + 1 * WSZ, attw + 2 * WSZ, attw + 2 * WSZ,
            attb + 0 * HID, attb + 1 * HID, attb + 2 * HID, attb + 2 * HID,
            p_den, p_Bx, p_Dx, p_Dx);
        dim3 ag(4, BATCH);
        attn_kernel<<<ag, 128, ATTN_SMEM>>>(p_den, p_Bx, p_Dx, sph, p_Ex);
        dim3 g1(NND / 128, 1, 2);
        gemm_tc<<<g1, 256, PLAIN_SMEM>>>(p_Ex, nullptr, 0,
            attw + 3 * WSZ, attw + 3 * WSZ, attw + 3 * WSZ, attw + 3 * WSZ,
            attb + 3 * HID, attb + 3 * HID, attb + 3 * HID, attb + 3 * HID,
            p_h, p_h, p_h, p_h);
    }
    pool_kernel<<<BATCH, 128>>>();
    mlp_kernel<<<BATCH, 128>>>(p_pool, m1w, m1b, p_t1, 128, 64, 1);
    mlp_kernel<<<BATCH, 128>>>(p_t1, m2w, m2b, p_t2, 64, 32, 1);
    mlp_kernel<<<BATCH, 128>>>(p_t2, m3w, m3b, out, 32, 10, 0);
}

// round 11
// speedup vs baseline: 1.1247x; 1.1247x over previous
#include <cuda_runtime.h>
#include <cuda_bf16.h>
#include <cstdint>

#define NND 16384
#define NE  262144
#define HID 128
#define BATCH 128
#define SEQ 128
#define NL 4
#define WSZ (HID*HID)

// smem word offsets
#define AHI 0        // 128 x 20 pairs (chunk K=32 -> 16 pairs, pad 20)
#define ALO 2560
#define WHI 5120     // 64 x 68 pairs (full K=128 -> 64 pairs, pad 68)
#define WLO 9472
#define OPW 13824
// edge tile overlay 128x68 = 8704 words (< OPW), idx after OPW

// ---------------- scratch ----------------
__device__ float g_h[NND * HID];
__device__ float g_eA[NE * HID];
__device__ float g_eB[NE * HID];
__device__ float g_eijA[NE * HID];
__device__ float g_eijB[NE * HID];
__device__ float g_Ax[NND * HID];
__device__ float g_Bx[NND * HID];
__device__ float g_Dx[NND * HID];
__device__ float g_Ex[NND * HID];
__device__ float g_num[NND * HID];
__device__ float g_den[NND * HID];
__device__ float g_part[2048 * 256];
__device__ float g_scN[HID], g_shN[HID], g_scE[HID], g_shE[HID];
__device__ float g_pool[BATCH * HID];
__device__ float g_t1[BATCH * 64];
__device__ float g_t2[BATCH * 32];
__device__ unsigned g_Wpack[24 * 16384];   // per matrix: hi[8192] then lo[8192], layout [n][kpair]
// edge sort
__device__ int g_cnt[NND];
__device__ int g_src2[NE];
__device__ int g_dst2[NE];
__device__ int g_perm[NE];

// ---------------- helpers ----------------
__device__ __forceinline__ void packpair(float f0, float f1, unsigned& hi, unsigned& lo) {
    __nv_bfloat162 h = __floats2bfloat162_rn(f0, f1);   // .x (low half) = f0 = even k
    float r0 = f0 - __bfloat162float(h.x);
    float r1 = f1 - __bfloat162float(h.y);
    __nv_bfloat162 l2 = __floats2bfloat162_rn(r0, r1);
    hi = *reinterpret_cast<unsigned*>(&h);
    lo = *reinterpret_cast<unsigned*>(&l2);
}
__device__ __forceinline__ void mma16(float* d, const unsigned* a, const unsigned* b) {
    asm volatile("mma.sync.aligned.m16n8k16.row.col.f32.bf16.bf16.f32 "
        "{%0,%1,%2,%3}, {%4,%5,%6,%7}, {%8,%9}, {%0,%1,%2,%3};"
        : "+f"(d[0]), "+f"(d[1]), "+f"(d[2]), "+f"(d[3])
        : "r"(a[0]), "r"(a[1]), "r"(a[2]), "r"(a[3]), "r"(b[0]), "r"(b[1]));
}
__device__ __forceinline__ void red4(float* p, float4 v) {
    asm volatile("red.global.add.v4.f32 [%0], {%1,%2,%3,%4};"
        :: "l"(p), "f"(v.x), "f"(v.y), "f"(v.z), "f"(v.w) : "memory");
}

// ---------------- weight pre-split: 24 matrices -> packed bf16 hi/lo [n][kpair] ----------------
__global__ void pack_w_kernel(const float* __restrict__ Aw, const float* __restrict__ Bw,
                              const float* __restrict__ Dw, const float* __restrict__ Ew,
                              const float* __restrict__ Cw, const float* __restrict__ attw) {
    int m = blockIdx.x;  // 0..19 conv (l*5+s), 20..23 attn
    const float* src;
    if (m < 20) {
        int l = m / 5, s = m % 5;
        src = ((s == 0) ? Aw : (s == 1) ? Bw : (s == 2) ? Dw : (s == 3) ? Ew : Cw) + l * WSZ;
    } else {
        src = attw + (m - 20) * WSZ;
    }
    unsigned* hi = g_Wpack + m * 16384;
    unsigned* lo = hi + 8192;
    for (int i = threadIdx.x; i < 8192; i += 256) {
        int n = i >> 6, kp = i & 63;
        float f0 = src[(2 * kp) * HID + n];
        float f1 = src[(2 * kp + 1) * HID + n];
        unsigned h, l2;
        packpair(f0, f1, h, l2);
        hi[i] = h;
        lo[i] = l2;
    }
}

// ---------------- init / zero ----------------
__global__ void init_kernel() {
    int i = blockIdx.x * 256 + threadIdx.x;
    float4 z = make_float4(0.f, 0.f, 0.f, 0.f);
    if (i < NND * HID / 4) { ((float4*)g_num)[i] = z; ((float4*)g_den)[i] = z; }
    if (i < 2048 * 64) ((float4*)g_part)[i] = z;
    if (i < NND / 4) ((int4*)g_cnt)[i] = make_int4(0, 0, 0, 0);
}
__global__ void zero_nd_kernel() {
    int i = blockIdx.x * 256 + threadIdx.x;
    float4 z = make_float4(0.f, 0.f, 0.f, 0.f);
    if (i < NND * HID / 4) { ((float4*)g_num)[i] = z; ((float4*)g_den)[i] = z; }
    if (i < 2048 * 64) ((float4*)g_part)[i] = z;
}

// ---------------- edge counting sort ----------------
__global__ void hist_kernel(const int* __restrict__ dst) {
    int i = blockIdx.x * blockDim.x + threadIdx.x;
    if (i < NE) atomicAdd(&g_cnt[dst[i]], 1);
}
__global__ __launch_bounds__(1024) void scan_kernel() {
    __shared__ int ssum[1024];
    int tid = threadIdx.x;
    int base = tid * 16;
    int loc[16]; int s = 0;
#pragma unroll
    for (int i = 0; i < 16; i++) { loc[i] = s; s += g_cnt[base + i]; }
    ssum[tid] = s;
    __syncthreads();
    for (int off = 1; off < 1024; off <<= 1) {
        int v = (tid >= off) ? ssum[tid - off] : 0;
        __syncthreads();
        ssum[tid] += v;
        __syncthreads();
    }
    int pre = (tid == 0) ? 0 : ssum[tid - 1];
#pragma unroll
    for (int i = 0; i < 16; i++) g_cnt[base + i] = pre + loc[i];
}
__global__ void scatter_kernel(const int* __restrict__ src, const int* __restrict__ dst) {
    int i = blockIdx.x * blockDim.x + threadIdx.x;
    if (i >= NE) return;
    int d = dst[i];
    int pos = atomicAdd(&g_cnt[d], 1);
    g_perm[pos] = i;
    g_src2[pos] = src[i];
    g_dst2[pos] = d;
}

// ---------------- input projection ----------------
__global__ void input_proj_kernel(const float* __restrict__ x, const float* __restrict__ pe,
                                  const float* __restrict__ nw, const float* __restrict__ nb,
                                  const float* __restrict__ pw, const float* __restrict__ pb) {
    int row = blockIdx.x;
    int c = threadIdx.x;
    __shared__ float xs[64];
    __shared__ float ps[16];
    if (c < 64) xs[c] = x[row * 64 + c];
    else if (c < 80) ps[c - 64] = pe[row * 16 + (c - 64)];
    __syncthreads();
    float acc;
    if (c < 112) {
        acc = nb[c];
#pragma unroll
        for (int k = 0; k < 64; k++) acc += xs[k] * nw[k * 112 + c];
    } else {
        int cc = c - 112;
        acc = pb[cc];
#pragma unroll
        for (int k = 0; k < 16; k++) acc += ps[k] * pw[k * 16 + cc];
    }
    g_h[row * HID + c] = acc;
}

// ================= split-bf16 GEMM, tile 128x64 (z-split N), multi-W via blockIdx.y ==========
__global__ __launch_bounds__(256, 3) void gemm_tc(
    const float* __restrict__ A, const float* __restrict__ foldE, int doFold,
    const unsigned* __restrict__ Wp0, const unsigned* __restrict__ Wp1,
    const unsigned* __restrict__ Wp2, const unsigned* __restrict__ Wp3,
    const float* __restrict__ b0, const float* __restrict__ b1,
    const float* __restrict__ b2, const float* __restrict__ b3,
    float* __restrict__ C0, float* __restrict__ C1,
    float* __restrict__ C2, float* __restrict__ C3) {
    int y = blockIdx.y, z = blockIdx.z;
    const unsigned* Wp = (y == 0) ? Wp0 : (y == 1) ? Wp1 : (y == 2) ? Wp2 : Wp3;
    const float* bb = (y == 0) ? b0 : (y == 1) ? b1 : (y == 2) ? b2 : b3;
    float* C = (y == 0) ? C0 : (y == 1) ? C1 : (y == 2) ? C2 : C3;

    extern __shared__ unsigned smu[];
    unsigned* AsHi = smu + AHI;
    unsigned* AsLo = smu + ALO;
    unsigned* WsHi = smu + WHI;
    unsigned* WsLo = smu + WLO;

    int tid = threadIdx.x, lane = tid & 31, wid = tid >> 5;
    int wm = wid & 3, wn = wid >> 2, g = lane >> 2, t = lane & 3;
    int r0 = blockIdx.x * 128;
    int arow = tid >> 1, acb = (tid & 1) * 16, pb = (tid & 1) * 8;

    // load full packed W (hi+lo) once
    {
        int nloc = tid >> 2, kb = (tid & 3) * 16;
        const unsigned* WHg = Wp + (size_t)(z * 64 + nloc) * 64 + kb;
        const unsigned* WLg = WHg + 8192;
#pragma unroll
        for (int q = 0; q < 4; q++) {
            *(uint4*)&WsHi[nloc * 68 + kb + q * 4] = *(const uint4*)&WHg[q * 4];
            *(uint4*)&WsLo[nloc * 68 + kb + q * 4] = *(const uint4*)&WLg[q * 4];
        }
    }

    float acc[2][4][4];
#pragma unroll
    for (int i = 0; i < 2; i++)
#pragma unroll
        for (int j = 0; j < 4; j++)
#pragma unroll
            for (int q = 0; q < 4; q++) acc[i][j][q] = 0.f;

    for (int k0 = 0; k0 < 128; k0 += 32) {
        __syncthreads();
        float vals[16];
#pragma unroll
        for (int q = 0; q < 4; q++) {
            int kc = k0 + acb + q * 4;
            float4 av = *(const float4*)&A[(size_t)(r0 + arow) * HID + kc];
            if (doFold) {
                float4 ev = *(const float4*)&foldE[(size_t)(r0 + arow) * HID + kc];
                float4 sc = *(const float4*)&g_scN[kc];
                float4 sh = *(const float4*)&g_shN[kc];
                av.x = fmaxf(av.x * sc.x + sh.x, 0.f) + ev.x;
                av.y = fmaxf(av.y * sc.y + sh.y, 0.f) + ev.y;
                av.z = fmaxf(av.z * sc.z + sh.z, 0.f) + ev.z;
                av.w = fmaxf(av.w * sc.w + sh.w, 0.f) + ev.w;
            }
            vals[q * 4 + 0] = av.x; vals[q * 4 + 1] = av.y;
            vals[q * 4 + 2] = av.z; vals[q * 4 + 3] = av.w;
        }
#pragma unroll
        for (int j = 0; j < 8; j++) {
            unsigned h, l2;
            packpair(vals[2 * j], vals[2 * j + 1], h, l2);
            AsHi[arow * 20 + pb + j] = h;
            AsLo[arow * 20 + pb + j] = l2;
        }
        __syncthreads();
#pragma unroll
        for (int hh = 0; hh < 2; hh++) {
            int pb16 = hh * 8;
            int P0h = (k0 >> 1) + pb16;
            unsigned ah[2][4], al[2][4];
#pragma unroll
            for (int mt = 0; mt < 2; mt++) {
                int rb = wm * 32 + mt * 16 + g;
                ah[mt][0] = AsHi[rb * 20 + pb16 + t];
                ah[mt][1] = AsHi[(rb + 8) * 20 + pb16 + t];
                ah[mt][2] = AsHi[rb * 20 + pb16 + t + 4];
                ah[mt][3] = AsHi[(rb + 8) * 20 + pb16 + t + 4];
                al[mt][0] = AsLo[rb * 20 + pb16 + t];
                al[mt][1] = AsLo[(rb + 8) * 20 + pb16 + t];
                al[mt][2] = AsLo[rb * 20 + pb16 + t + 4];
                al[mt][3] = AsLo[(rb + 8) * 20 + pb16 + t + 4];
            }
#pragma unroll
            for (int nt = 0; nt < 4; nt++) {
                int ncol = wn * 32 + nt * 8 + g;
                unsigned bh[2] = { WsHi[ncol * 68 + P0h + t], WsHi[ncol * 68 + P0h + t + 4] };
                unsigned bl[2] = { WsLo[ncol * 68 + P0h + t], WsLo[ncol * 68 + P0h + t + 4] };
#pragma unroll
                for (int mt = 0; mt < 2; mt++) {
                    mma16(acc[mt][nt], ah[mt], bh);
                    mma16(acc[mt][nt], al[mt], bh);
                    mma16(acc[mt][nt], ah[mt], bl);
                }
            }
        }
    }
#pragma unroll
    for (int mt = 0; mt < 2; mt++) {
#pragma unroll
        for (int nt = 0; nt < 4; nt++) {
            int c = z * 64 + wn * 32 + nt * 8 + 2 * t;
            float bx = bb[c], by = bb[c + 1];
            int r = r0 + wm * 32 + mt * 16 + g;
            *(float2*)&C[(size_t)r * HID + c] = make_float2(acc[mt][nt][0] + bx, acc[mt][nt][1] + by);
            *(float2*)&C[(size_t)(r + 8) * HID + c] = make_float2(acc[mt][nt][2] + bx, acc[mt][nt][3] + by);
        }
    }
}

// ================= edge GEMM (sorted), split-bf16, fold loader + segment-reduce epilogue =====
__global__ __launch_bounds__(256, 3) void gemm_tc_edge(
    const float* __restrict__ A, const float* __restrict__ foldE, float* __restrict__ foldOut,
    const unsigned* __restrict__ Wp, const float* __restrict__ bias,
    float* __restrict__ C,
    const float* __restrict__ Dx, const float* __restrict__ Ex, const float* __restrict__ Bx,
    int doStats, int permA, int permF, int writeC, int writeFold) {
    extern __shared__ unsigned smu[];
    unsigned* AsHi = smu + AHI;
    unsigned* AsLo = smu + ALO;
    unsigned* WsHi = smu + WHI;
    unsigned* WsLo = smu + WLO;
    float* tile = (float*)smu;           // overlay 128x68 after mainloop
    int* sidx = (int*)(smu + OPW);
    int* didx = sidx + 128;
    int* pidx = didx + 128;

    int tid = threadIdx.x, lane = tid & 31, wid = tid >> 5;
    int wm = wid & 3, wn = wid >> 2, g = lane >> 2, t = lane & 3;
    int r0 = blockIdx.x * 128;
    int z = blockIdx.z;
    int arow = tid >> 1, acb = (tid & 1) * 16, pb = (tid & 1) * 8;

    if (tid < 128) {
        sidx[tid] = g_src2[r0 + tid];
        didx[tid] = g_dst2[r0 + tid];
        pidx[tid] = g_perm[r0 + tid];
    }
    // load full packed W once
    {
        int nloc = tid >> 2, kb = (tid & 3) * 16;
        const unsigned* WHg = Wp + (size_t)(z * 64 + nloc) * 64 + kb;
        const unsigned* WLg = WHg + 8192;
#pragma unroll
        for (int q = 0; q < 4; q++) {
            *(uint4*)&WsHi[nloc * 68 + kb + q * 4] = *(const uint4*)&WHg[q * 4];
            *(uint4*)&WsLo[nloc * 68 + kb + q * 4] = *(const uint4*)&WLg[q * 4];
        }
    }
    __syncthreads();

    float acc[2][4][4];
#pragma unroll
    for (int i = 0; i < 2; i++)
#pragma unroll
        for (int j = 0; j < 4; j++)
#pragma unroll
            for (int q = 0; q < 4; q++) acc[i][j][q] = 0.f;

    int doFold = (foldE != nullptr);
    int aIdx = permA ? pidx[arow] : (r0 + arow);
    int fIdx = permF ? pidx[arow] : (r0 + arow);
    int wF = writeFold && (z == 0);

    for (int k0 = 0; k0 < 128; k0 += 32) {
        if (k0) __syncthreads();
        float vals[16];
#pragma unroll
        for (int q = 0; q < 4; q++) {
            int kc = k0 + acb + q * 4;
            float4 av = *(const float4*)&A[(size_t)aIdx * HID + kc];
            if (doFold) {
                float4 ev = *(const float4*)&foldE[(size_t)fIdx * HID + kc];
                float4 sc = *(const float4*)&g_scE[kc];
                float4 sh = *(const float4*)&g_shE[kc];
                av.x = fmaxf(av.x * sc.x + sh.x, 0.f) + ev.x;
                av.y = fmaxf(av.y * sc.y + sh.y, 0.f) + ev.y;
                av.z = fmaxf(av.z * sc.z + sh.z, 0.f) + ev.z;
                av.w = fmaxf(av.w * sc.w + sh.w, 0.f) + ev.w;
                if (wF) *(float4*)&foldOut[(size_t)(r0 + arow) * HID + kc] = av;
            }
            vals[q * 4 + 0] = av.x; vals[q * 4 + 1] = av.y;
            vals[q * 4 + 2] = av.z; vals[q * 4 + 3] = av.w;
        }
#pragma unroll
        for (int j = 0; j < 8; j++) {
            unsigned h, l2;
            packpair(vals[2 * j], vals[2 * j + 1], h, l2);
            AsHi[arow * 20 + pb + j] = h;
            AsLo[arow * 20 + pb + j] = l2;
        }
        __syncthreads();
#pragma unroll
        for (int hh = 0; hh < 2; hh++) {
            int pb16 = hh * 8;
            int P0h = (k0 >> 1) + pb16;
            unsigned ah[2][4], al[2][4];
#pragma unroll
            for (int mt = 0; mt < 2; mt++) {
                int rb = wm * 32 + mt * 16 + g;
                ah[mt][0] = AsHi[rb * 20 + pb16 + t];
                ah[mt][1] = AsHi[(rb + 8) * 20 + pb16 + t];
                ah[mt][2] = AsHi[rb * 20 + pb16 + t + 4];
                ah[mt][3] = AsHi[(rb + 8) * 20 + pb16 + t + 4];
                al[mt][0] = AsLo[rb * 20 + pb16 + t];
                al[mt][1] = AsLo[(rb + 8) * 20 + pb16 + t];
                al[mt][2] = AsLo[rb * 20 + pb16 + t + 4];
                al[mt][3] = AsLo[(rb + 8) * 20 + pb16 + t + 4];
            }
#pragma unroll
            for (int nt = 0; nt < 4; nt++) {
                int ncol = wn * 32 + nt * 8 + g;
                unsigned bh[2] = { WsHi[ncol * 68 + P0h + t], WsHi[ncol * 68 + P0h + t + 4] };
                unsigned bl[2] = { WsLo[ncol * 68 + P0h + t], WsLo[ncol * 68 + P0h + t + 4] };
#pragma unroll
                for (int mt = 0; mt < 2; mt++) {
                    mma16(acc[mt][nt], ah[mt], bh);
                    mma16(acc[mt][nt], al[mt], bh);
                    mma16(acc[mt][nt], ah[mt], bl);
                }
            }
        }
    }
    __syncthreads();
    // stage accumulators to smem tile (overlays operand region)
#pragma unroll
    for (int mt = 0; mt < 2; mt++) {
#pragma unroll
        for (int nt = 0; nt < 4; nt++) {
            int cc = wn * 32 + nt * 8 + 2 * t;
            int r = wm * 32 + mt * 16 + g;
            tile[r * 68 + cc] = acc[mt][nt][0];
            tile[r * 68 + cc + 1] = acc[mt][nt][1];
            tile[(r + 8) * 68 + cc] = acc[mt][nt][2];
            tile[(r + 8) * 68 + cc + 1] = acc[mt][nt][3];
        }
    }
    __syncthreads();
    // epilogue: 16 threads x 4ch per row-group of 8 sorted rows; segment-reduce on dst runs
    {
        int c4l = (tid & 15) * 4;
        int c4g = z * 64 + c4l;
        int chunk = tid >> 4;  // 0..15, 8 rows each
        float4 bcv = *(const float4*)&bias[c4g];
        float4 s1v = make_float4(0.f, 0.f, 0.f, 0.f);
        float4 s2v = make_float4(0.f, 0.f, 0.f, 0.f);
        float4 accN = make_float4(0.f, 0.f, 0.f, 0.f);
        float4 accD = make_float4(0.f, 0.f, 0.f, 0.f);
        int curd = didx[chunk * 8];
#pragma unroll
        for (int rr = 0; rr < 8; rr++) {
            int r = chunk * 8 + rr;
            int d = didx[r], s = sidx[r];
            if (d != curd) {
                red4(&g_num[(size_t)curd * HID + c4g], accN);
                red4(&g_den[(size_t)curd * HID + c4g], accD);
                accN = make_float4(0.f, 0.f, 0.f, 0.f);
                accD = make_float4(0.f, 0.f, 0.f, 0.f);
                curd = d;
            }
            float4 tv = *(float4*)&tile[r * 68 + c4l];
            float4 dx = *(const float4*)&Dx[(size_t)d * HID + c4g];
            float4 ex = *(const float4*)&Ex[(size_t)s * HID + c4g];
            float4 bx = *(const float4*)&Bx[(size_t)s * HID + c4g];
            float4 v;
            v.x = tv.x + bcv.x + dx.x + ex.x;
            v.y = tv.y + bcv.y + dx.y + ex.y;
            v.z = tv.z + bcv.z + dx.z + ex.z;
            v.w = tv.w + bcv.w + dx.w + ex.w;
            if (writeC) *(float4*)&C[(size_t)(r0 + r) * HID + c4g] = v;
            float4 sg;
            sg.x = 1.f / (1.f + __expf(-v.x));
            sg.y = 1.f / (1.f + __expf(-v.y));
            sg.z = 1.f / (1.f + __expf(-v.z));
            sg.w = 1.f / (1.f + __expf(-v.w));
            accN.x += sg.x * bx.x; accN.y += sg.y * bx.y;
            accN.z += sg.z * bx.z; accN.w += sg.w * bx.w;
            accD.x += sg.x; accD.y += sg.y; accD.z += sg.z; accD.w += sg.w;
            s1v.x += v.x; s1v.y += v.y; s1v.z += v.z; s1v.w += v.w;
            s2v.x += v.x * v.x; s2v.y += v.y * v.y; s2v.z += v.z * v.z; s2v.w += v.w * v.w;
        }
        red4(&g_num[(size_t)curd * HID + c4g], accN);
        red4(&g_den[(size_t)curd * HID + c4g], accD);
        if (doStats) {
            red4(&g_part[blockIdx.x * 256 + c4g], s1v);
            red4(&g_part[blockIdx.x * 256 + 128 + c4g], s2v);
        }
    }
}

// ---------------- h_new = Ax + num/(den+eps) fused with BN partials ----------------
__global__ void node_hnew_stats_kernel() {
    int c = threadIdx.x;
    float s = 0.f, ss = 0.f;
    for (int r = blockIdx.x; r < NND; r += gridDim.x) {
        int i = r * HID + c;
        float v = g_Ax[i] + g_num[i] / (g_den[i] + 1e-6f);
        g_Ax[i] = v;
        s += v; ss += v * v;
    }
    g_part[blockIdx.x * 256 + c] = s;
    g_part[blockIdx.x * 256 + 128 + c] = ss;
}

// ---------------- BN finalize ----------------
__global__ void bn_finalize2(int G, float invM, const float* __restrict__ gamma,
                             const float* __restrict__ beta,
                             float* __restrict__ scale, float* __restrict__ shift) {
    int c = blockIdx.x;
    int tid = threadIdx.x;
    double s = 0.0, ss = 0.0;
    for (int gi = tid; gi < G; gi += 256) {
        s  += (double)g_part[gi * 256 + c];
        ss += (double)g_part[gi * 256 + 128 + c];
    }
    __shared__ double rs[256], rss[256];
    rs[tid] = s; rss[tid] = ss;
    __syncthreads();
    for (int o = 128; o > 0; o >>= 1) {
        if (tid < o) { rs[tid] += rs[tid + o]; rss[tid] += rss[tid + o]; }
        __syncthreads();
    }
    if (tid == 0) {
        double mu = rs[0] * (double)invM;
        double var = rss[0] * (double)invM - mu * mu;
        float inv = rsqrtf((float)var + 1e-5f);
        float scv = gamma[c] * inv;
        scale[c] = scv;
        shift[c] = beta[c] - (float)mu * scv;
    }
}

// ---------------- dense attention per (head, batch graph) ----------------
__global__ void attn_kernel(const float* __restrict__ q, const float* __restrict__ k,
                            const float* __restrict__ v, const float* __restrict__ sph,
                            float* __restrict__ o) {
    extern __shared__ float smf[];
    float* ks = smf;
    float* vs = smf + 128 * 36;
    float* ps = smf + 2 * 128 * 36;
    int head = blockIdx.x, b = blockIdx.y;
    int s = threadIdx.x;
    int nodebase = (b * SEQ + s) * HID + head * 32;
    float qr[32];
#pragma unroll
    for (int d4 = 0; d4 < 8; d4++) {
        float4 tq = *(const float4*)&q[nodebase + d4 * 4];
        qr[d4 * 4] = tq.x; qr[d4 * 4 + 1] = tq.y; qr[d4 * 4 + 2] = tq.z; qr[d4 * 4 + 3] = tq.w;
        *(float4*)&ks[s * 36 + d4 * 4] = *(const float4*)&k[nodebase + d4 * 4];
        *(float4*)&vs[s * 36 + d4 * 4] = *(const float4*)&v[nodebase + d4 * 4];
    }
    __syncthreads();
    const float isd = 0.17677669529663687f;
    for (int t = 0; t < SEQ; t++) {
        float acc = 0.f;
#pragma unroll
        for (int d4 = 0; d4 < 8; d4++) {
            float4 kk = *(float4*)&ks[t * 36 + d4 * 4];
            acc += qr[d4 * 4] * kk.x + qr[d4 * 4 + 1] * kk.y +
                   qr[d4 * 4 + 2] * kk.z + qr[d4 * 4 + 3] * kk.w;
        }
        ps[s * 133 + t] = acc * isd;
    }
    __syncthreads();
    const float* sb = sph + b * SEQ * SEQ;
    for (int i = s; i < SEQ * SEQ; i += 128) {
        int s2 = i >> 7, t2 = i & 127;
        ps[s2 * 133 + t2] *= sb[i];
    }
    __syncthreads();
    float mx = -1e30f;
    for (int t = 0; t < SEQ; t++) mx = fmaxf(mx, ps[s * 133 + t]);
    float sum = 0.f;
    for (int t = 0; t < SEQ; t++) {
        float e = __expf(ps[s * 133 + t] - mx);
        ps[s * 133 + t] = e;
        sum += e;
    }
    float inv = 1.f / sum;
    float acc[32];
#pragma unroll
    for (int d = 0; d < 32; d++) acc[d] = 0.f;
    for (int t = 0; t < SEQ; t++) {
        float p = ps[s * 133 + t] * inv;
#pragma unroll
        for (int d4 = 0; d4 < 8; d4++) {
            float4 vvv = *(float4*)&vs[t * 36 + d4 * 4];
            acc[d4 * 4] += p * vvv.x; acc[d4 * 4 + 1] += p * vvv.y;
            acc[d4 * 4 + 2] += p * vvv.z; acc[d4 * 4 + 3] += p * vvv.w;
        }
    }
#pragma unroll
    for (int d4 = 0; d4 < 8; d4++) {
        float4 t4 = make_float4(acc[d4 * 4], acc[d4 * 4 + 1], acc[d4 * 4 + 2], acc[d4 * 4 + 3]);
        *(float4*)&o[nodebase + d4 * 4] = t4;
    }
}

// ---------------- mean pool + tiny MLP ----------------
__global__ void pool_kernel() {
    int b = blockIdx.x, c = threadIdx.x;
    float s = 0.f;
    for (int i = 0; i < SEQ; i++) s += g_h[(b * SEQ + i) * HID + c];
    g_pool[b * HID + c] = s * (1.f / 128.f);
}
__global__ void mlp_kernel(const float* __restrict__ in, const float* __restrict__ W,
                           const float* __restrict__ bias, float* __restrict__ out,
                           int K, int Ncol, int doRelu) {
    int r = blockIdx.x;
    __shared__ float xs[128];
    if ((int)threadIdx.x < K) xs[threadIdx.x] = in[r * K + threadIdx.x];
    __syncthreads();
    int c = threadIdx.x;
    if (c < Ncol) {
        float acc = bias[c];
        for (int k = 0; k < K; k++) acc += xs[k] * W[k * Ncol + c];
        if (doRelu) acc = fmaxf(acc, 0.f);
        out[r * Ncol + c] = acc;
    }
}

// ---------------- launch ----------------
extern "C" void kernel_launch(void* const* d_in, const int* in_sizes, int n_in,
                              void* d_out, int out_size) {
    const float* x        = (const float*)d_in[0];
    const float* pe       = (const float*)d_in[1];
    const float* edge_attr= (const float*)d_in[2];
    const float* sph      = (const float*)d_in[3];
    const float* node_w   = (const float*)d_in[4];
    const float* node_b   = (const float*)d_in[5];
    const float* pe_w     = (const float*)d_in[6];
    const float* pe_b     = (const float*)d_in[7];
    const float* Aw       = (const float*)d_in[8];
    const float* Ab       = (const float*)d_in[9];
    const float* Bw       = (const float*)d_in[10];
    const float* Bb       = (const float*)d_in[11];
    const float* Cw       = (const float*)d_in[12];
    const float* Cb       = (const float*)d_in[13];
    const float* Dw       = (const float*)d_in[14];
    const float* Db       = (const float*)d_in[15];
    const float* Ew       = (const float*)d_in[16];
    const float* Eb       = (const float*)d_in[17];
    const float* bnxg     = (const float*)d_in[18];
    const float* bnxb     = (const float*)d_in[19];
    const float* bneg     = (const float*)d_in[20];
    const float* bneb     = (const float*)d_in[21];
    const float* attw     = (const float*)d_in[22];
    const float* attb     = (const float*)d_in[23];
    const float* m1w      = (const float*)d_in[24];
    const float* m1b      = (const float*)d_in[25];
    const float* m2w      = (const float*)d_in[26];
    const float* m2b      = (const float*)d_in[27];
    const float* m3w      = (const float*)d_in[28];
    const float* m3b      = (const float*)d_in[29];
    const int*   ei       = (const int*)d_in[30];
    float* out = (float*)d_out;

    float *p_h, *p_eA, *p_eB, *p_eijA, *p_eijB, *p_Ax, *p_Bx, *p_Dx, *p_Ex, *p_num, *p_den;
    float *p_scN, *p_shN, *p_scE, *p_shE, *p_pool, *p_t1, *p_t2;
    unsigned* p_Wpack;
    cudaGetSymbolAddress((void**)&p_h,    g_h);
    cudaGetSymbolAddress((void**)&p_eA,   g_eA);
    cudaGetSymbolAddress((void**)&p_eB,   g_eB);
    cudaGetSymbolAddress((void**)&p_eijA, g_eijA);
    cudaGetSymbolAddress((void**)&p_eijB, g_eijB);
    cudaGetSymbolAddress((void**)&p_Ax,   g_Ax);
    cudaGetSymbolAddress((void**)&p_Bx,   g_Bx);
    cudaGetSymbolAddress((void**)&p_Dx,   g_Dx);
    cudaGetSymbolAddress((void**)&p_Ex,   g_Ex);
    cudaGetSymbolAddress((void**)&p_num,  g_num);
    cudaGetSymbolAddress((void**)&p_den,  g_den);
    cudaGetSymbolAddress((void**)&p_scN,  g_scN);
    cudaGetSymbolAddress((void**)&p_shN,  g_shN);
    cudaGetSymbolAddress((void**)&p_scE,  g_scE);
    cudaGetSymbolAddress((void**)&p_shE,  g_shE);
    cudaGetSymbolAddress((void**)&p_pool, g_pool);
    cudaGetSymbolAddress((void**)&p_t1,   g_t1);
    cudaGetSymbolAddress((void**)&p_t2,   g_t2);
    cudaGetSymbolAddress((void**)&p_Wpack, g_Wpack);

    float* eij_bufs[2] = { p_eijA, p_eijB };
    float* e_bufs[2]   = { p_eA, p_eB };

    const int* src = ei;
    const int* dst = ei + NE;
    const int ATTN_SMEM = (2 * 128 * 36 + 128 * 133) * 4;
    const int PLAIN_SMEM = OPW * 4;                   // 55296
    const int EDGE_SMEM = (OPW + 384) * 4;            // 56832
    cudaFuncSetAttribute(attn_kernel, cudaFuncAttributeMaxDynamicSharedMemorySize, ATTN_SMEM);
    cudaFuncSetAttribute(gemm_tc, cudaFuncAttributeMaxDynamicSharedMemorySize, PLAIN_SMEM);
    cudaFuncSetAttribute(gemm_tc_edge, cudaFuncAttributeMaxDynamicSharedMemorySize, EDGE_SMEM);

    init_kernel<<<2048, 256>>>();
    pack_w_kernel<<<24, 256>>>(Aw, Bw, Dw, Ew, Cw, attw);
    hist_kernel<<<NE / 256, 256>>>(dst);
    scan_kernel<<<1, 1024>>>();
    scatter_kernel<<<NE / 256, 256>>>(src, dst);
    input_proj_kernel<<<NND, 128>>>(x, pe, node_w, node_b, pe_w, pe_b);

    for (int l = 0; l < NL; l++) {
        if (l > 0) zero_nd_kernel<<<2048, 256>>>();
        dim3 g4(NND / 128, 4, 2);
        gemm_tc<<<g4, 256, PLAIN_SMEM>>>(p_h, nullptr, 0,
            p_Wpack + (l * 5 + 0) * 16384, p_Wpack + (l * 5 + 1) * 16384,
            p_Wpack + (l * 5 + 2) * 16384, p_Wpack + (l * 5 + 3) * 16384,
            Ab + l * HID, Bb + l * HID, Db + l * HID, Eb + l * HID,
            p_Ax, p_Bx, p_Dx, p_Ex);
        const float* eA    = (l == 0) ? edge_attr : eij_bufs[(l - 1) & 1];
        float* eij_out     = eij_bufs[l & 1];
        const float* foldE = (l == 0) ? nullptr : ((l == 1) ? edge_attr : e_bufs[(l - 1) & 1]);
        float* fold_out    = e_bufs[l & 1];
        int permA = (l == 0) ? 1 : 0;
        int permF = (l == 1) ? 1 : 0;
        int last = (l == NL - 1);
        dim3 ge(NE / 128, 1, 2);
        gemm_tc_edge<<<ge, 256, EDGE_SMEM>>>(
            eA, foldE, fold_out, p_Wpack + (l * 5 + 4) * 16384, Cb + l * HID, eij_out,
            p_Dx, p_Ex, p_Bx, last ? 0 : 1, permA, permF,
            last ? 0 : 1, last ? 0 : 1);
        if (!last)
            bn_finalize2<<<HID, 256>>>(2048, 1.f / NE, bneg + l * HID, bneb + l * HID, p_scE, p_shE);
        node_hnew_stats_kernel<<<1024, 128>>>();
        bn_finalize2<<<HID, 256>>>(1024, 1.f / NND, bnxg + l * HID, bnxb + l * HID, p_scN, p_shN);
        dim3 g3(NND / 128, 3, 2);
        gemm_tc<<<g3, 256, PLAIN_SMEM>>>(p_Ax, p_h, 1,
            p_Wpack + 20 * 16384, p_Wpack + 21 * 16384,
            p_Wpack + 22 * 16384, p_Wpack + 22 * 16384,
            attb + 0 * HID, attb + 1 * HID, attb + 2 * HID, attb + 2 * HID,
            p_den, p_Bx, p_Dx, p_Dx);
        dim3 ag(4, BATCH);
        attn_kernel<<<ag, 128, ATTN_SMEM>>>(p_den, p_Bx, p_Dx, sph, p_Ex);
        dim3 g1(NND / 128, 1, 2);
        gemm_tc<<<g1, 256, PLAIN_SMEM>>>(p_Ex, nullptr, 0,
            p_Wpack + 23 * 16384, p_Wpack + 23 * 16384,
            p_Wpack + 23 * 16384, p_Wpack + 23 * 16384,
            attb + 3 * HID, attb + 3 * HID, attb + 3 * HID, attb + 3 * HID,
            p_h, p_h, p_h, p_h);
    }
    pool_kernel<<<BATCH, 128>>>();
    mlp_kernel<<<BATCH, 128>>>(p_pool, m1w, m1b, p_t1, 128, 64, 1);
    mlp_kernel<<<BATCH, 128>>>(p_t1, m2w, m2b, p_t2, 64, 32, 1);
    mlp_kernel<<<BATCH, 128>>>(p_t2, m3w, m3b, out, 32, 10, 0);
}

// round 13
// speedup vs baseline: 1.1846x; 1.0533x over previous
#include <cuda_runtime.h>
#include <cuda_bf16.h>
#include <cstdint>

#define NND 16384
#define NE  262144
#define HID 128
#define BATCH 128
#define SEQ 128
#define NL 4
#define WSZ (HID*HID)

// smem word offsets
#define AHI 0        // 128 x 20 pairs
#define ALO 2560
#define WHI 5120     // 64 x 68 pairs
#define WLO 9472
#define OPW 13824

// ---------------- scratch ----------------
__device__ float g_h[NND * HID];
__device__ float g_eA[NE * HID];
__device__ float g_eB[NE * HID];
__device__ float g_eijA[NE * HID];
__device__ float g_eijB[NE * HID];
__device__ float g_Ax[NND * HID];
__device__ float g_Bx[NND * HID];
__device__ float g_Dx[NND * HID];
__device__ float g_Ex[NND * HID];
__device__ float g_num[NND * HID];
__device__ float g_den[NND * HID];
__device__ float g_part[2048 * 256];
__device__ float g_scN[HID], g_shN[HID], g_scE[HID], g_shE[HID];
__device__ float g_pool[BATCH * HID];
__device__ float g_t1[BATCH * 64];
__device__ float g_t2[BATCH * 32];
__device__ unsigned g_Wpack[24 * 16384];   // per matrix: hi[8192] then lo[8192], layout [n][kpair]
// edge sort
__device__ int g_cnt[NND];
__device__ int g_src2[NE];
__device__ int g_dst2[NE];
__device__ int g_perm[NE];

// ---------------- helpers ----------------
__device__ __forceinline__ void packpair(float f0, float f1, unsigned& hi, unsigned& lo) {
    __nv_bfloat162 h = __floats2bfloat162_rn(f0, f1);
    float r0 = f0 - __bfloat162float(h.x);
    float r1 = f1 - __bfloat162float(h.y);
    __nv_bfloat162 l2 = __floats2bfloat162_rn(r0, r1);
    hi = *reinterpret_cast<unsigned*>(&h);
    lo = *reinterpret_cast<unsigned*>(&l2);
}
__device__ __forceinline__ void mma16(float* d, const unsigned* a, const unsigned* b) {
    asm volatile("mma.sync.aligned.m16n8k16.row.col.f32.bf16.bf16.f32 "
        "{%0,%1,%2,%3}, {%4,%5,%6,%7}, {%8,%9}, {%0,%1,%2,%3};"
        : "+f"(d[0]), "+f"(d[1]), "+f"(d[2]), "+f"(d[3])
        : "r"(a[0]), "r"(a[1]), "r"(a[2]), "r"(a[3]), "r"(b[0]), "r"(b[1]));
}
__device__ __forceinline__ void red4(float* p, float4 v) {
    asm volatile("red.global.add.v4.f32 [%0], {%1,%2,%3,%4};"
        :: "l"(p), "f"(v.x), "f"(v.y), "f"(v.z), "f"(v.w) : "memory");
}

// ---------------- weight pre-split ----------------
__global__ void pack_w_kernel(const float* __restrict__ Aw, const float* __restrict__ Bw,
                              const float* __restrict__ Dw, const float* __restrict__ Ew,
                              const float* __restrict__ Cw, const float* __restrict__ attw) {
    int m = blockIdx.x;
    const float* src;
    if (m < 20) {
        int l = m / 5, s = m % 5;
        src = ((s == 0) ? Aw : (s == 1) ? Bw : (s == 2) ? Dw : (s == 3) ? Ew : Cw) + l * WSZ;
    } else {
        src = attw + (m - 20) * WSZ;
    }
    unsigned* hi = g_Wpack + m * 16384;
    unsigned* lo = hi + 8192;
    for (int i = threadIdx.x; i < 8192; i += 256) {
        int n = i >> 6, kp = i & 63;
        float f0 = src[(2 * kp) * HID + n];
        float f1 = src[(2 * kp + 1) * HID + n];
        unsigned h, l2;
        packpair(f0, f1, h, l2);
        hi[i] = h;
        lo[i] = l2;
    }
}

// ---------------- init / zero ----------------
__global__ void init_kernel() {
    int i = blockIdx.x * 256 + threadIdx.x;
    float4 z = make_float4(0.f, 0.f, 0.f, 0.f);
    if (i < NND * HID / 4) { ((float4*)g_num)[i] = z; ((float4*)g_den)[i] = z; }
    if (i < 2048 * 64) ((float4*)g_part)[i] = z;
    if (i < NND / 4) ((int4*)g_cnt)[i] = make_int4(0, 0, 0, 0);
}
__global__ void zero_nd_kernel() {
    int i = blockIdx.x * 256 + threadIdx.x;
    float4 z = make_float4(0.f, 0.f, 0.f, 0.f);
    if (i < NND * HID / 4) { ((float4*)g_num)[i] = z; ((float4*)g_den)[i] = z; }
    if (i < 2048 * 64) ((float4*)g_part)[i] = z;
}

// ---------------- edge counting sort ----------------
__global__ void hist_kernel(const int* __restrict__ dst) {
    int i = blockIdx.x * blockDim.x + threadIdx.x;
    if (i < NE) atomicAdd(&g_cnt[dst[i]], 1);
}
__global__ __launch_bounds__(1024) void scan_kernel() {
    __shared__ int ssum[1024];
    int tid = threadIdx.x;
    int base = tid * 16;
    int loc[16]; int s = 0;
#pragma unroll
    for (int i = 0; i < 16; i++) { loc[i] = s; s += g_cnt[base + i]; }
    ssum[tid] = s;
    __syncthreads();
    for (int off = 1; off < 1024; off <<= 1) {
        int v = (tid >= off) ? ssum[tid - off] : 0;
        __syncthreads();
        ssum[tid] += v;
        __syncthreads();
    }
    int pre = (tid == 0) ? 0 : ssum[tid - 1];
#pragma unroll
    for (int i = 0; i < 16; i++) g_cnt[base + i] = pre + loc[i];
}
__global__ void scatter_kernel(const int* __restrict__ src, const int* __restrict__ dst) {
    int i = blockIdx.x * blockDim.x + threadIdx.x;
    if (i >= NE) return;
    int d = dst[i];
    int pos = atomicAdd(&g_cnt[d], 1);
    g_perm[pos] = i;
    g_src2[pos] = src[i];
    g_dst2[pos] = d;
}

// ---------------- input projection ----------------
__global__ void input_proj_kernel(const float* __restrict__ x, const float* __restrict__ pe,
                                  const float* __restrict__ nw, const float* __restrict__ nb,
                                  const float* __restrict__ pw, const float* __restrict__ pb) {
    int row = blockIdx.x;
    int c = threadIdx.x;
    __shared__ float xs[64];
    __shared__ float ps[16];
    if (c < 64) xs[c] = x[row * 64 + c];
    else if (c < 80) ps[c - 64] = pe[row * 16 + (c - 64)];
    __syncthreads();
    float acc;
    if (c < 112) {
        acc = nb[c];
#pragma unroll
        for (int k = 0; k < 64; k++) acc += xs[k] * nw[k * 112 + c];
    } else {
        int cc = c - 112;
        acc = pb[cc];
#pragma unroll
        for (int k = 0; k < 16; k++) acc += ps[k] * pw[k * 16 + cc];
    }
    g_h[row * HID + c] = acc;
}

// ================= split-bf16 GEMM, tile 128x64 (z-split N), multi-W via blockIdx.y ==========
__global__ __launch_bounds__(256, 3) void gemm_tc(
    const float* __restrict__ A, const float* __restrict__ foldE, int doFold,
    const unsigned* __restrict__ Wp0, const unsigned* __restrict__ Wp1,
    const unsigned* __restrict__ Wp2, const unsigned* __restrict__ Wp3,
    const float* __restrict__ b0, const float* __restrict__ b1,
    const float* __restrict__ b2, const float* __restrict__ b3,
    float* __restrict__ C0, float* __restrict__ C1,
    float* __restrict__ C2, float* __restrict__ C3) {
    int y = blockIdx.y, z = blockIdx.z;
    const unsigned* Wp = (y == 0) ? Wp0 : (y == 1) ? Wp1 : (y == 2) ? Wp2 : Wp3;
    const float* bb = (y == 0) ? b0 : (y == 1) ? b1 : (y == 2) ? b2 : b3;
    float* C = (y == 0) ? C0 : (y == 1) ? C1 : (y == 2) ? C2 : C3;

    extern __shared__ unsigned smu[];
    unsigned* AsHi = smu + AHI;
    unsigned* AsLo = smu + ALO;
    unsigned* WsHi = smu + WHI;
    unsigned* WsLo = smu + WLO;

    int tid = threadIdx.x, lane = tid & 31, wid = tid >> 5;
    int wm = wid & 3, wn = wid >> 2, g = lane >> 2, t = lane & 3;
    int r0 = blockIdx.x * 128;
    int arow = tid >> 1, acb = (tid & 1) * 16, pb = (tid & 1) * 8;

    {
        int nloc = tid >> 2, kb = (tid & 3) * 16;
        const unsigned* WHg = Wp + (size_t)(z * 64 + nloc) * 64 + kb;
        const unsigned* WLg = WHg + 8192;
#pragma unroll
        for (int q = 0; q < 4; q++) {
            *(uint4*)&WsHi[nloc * 68 + kb + q * 4] = *(const uint4*)&WHg[q * 4];
            *(uint4*)&WsLo[nloc * 68 + kb + q * 4] = *(const uint4*)&WLg[q * 4];
        }
    }

    float acc[2][4][4];
#pragma unroll
    for (int i = 0; i < 2; i++)
#pragma unroll
        for (int j = 0; j < 4; j++)
#pragma unroll
            for (int q = 0; q < 4; q++) acc[i][j][q] = 0.f;

    for (int k0 = 0; k0 < 128; k0 += 32) {
        __syncthreads();
        float vals[16];
#pragma unroll
        for (int q = 0; q < 4; q++) {
            int kc = k0 + acb + q * 4;
            float4 av = *(const float4*)&A[(size_t)(r0 + arow) * HID + kc];
            if (doFold) {
                float4 ev = *(const float4*)&foldE[(size_t)(r0 + arow) * HID + kc];
                float4 sc = *(const float4*)&g_scN[kc];
                float4 sh = *(const float4*)&g_shN[kc];
                av.x = fmaxf(av.x * sc.x + sh.x, 0.f) + ev.x;
                av.y = fmaxf(av.y * sc.y + sh.y, 0.f) + ev.y;
                av.z = fmaxf(av.z * sc.z + sh.z, 0.f) + ev.z;
                av.w = fmaxf(av.w * sc.w + sh.w, 0.f) + ev.w;
            }
            vals[q * 4 + 0] = av.x; vals[q * 4 + 1] = av.y;
            vals[q * 4 + 2] = av.z; vals[q * 4 + 3] = av.w;
        }
#pragma unroll
        for (int j = 0; j < 8; j++) {
            unsigned h, l2;
            packpair(vals[2 * j], vals[2 * j + 1], h, l2);
            AsHi[arow * 20 + pb + j] = h;
            AsLo[arow * 20 + pb + j] = l2;
        }
        __syncthreads();
#pragma unroll
        for (int hh = 0; hh < 2; hh++) {
            int pb16 = hh * 8;
            int P0h = (k0 >> 1) + pb16;
            unsigned ah[2][4], al[2][4];
#pragma unroll
            for (int mt = 0; mt < 2; mt++) {
                int rb = wm * 32 + mt * 16 + g;
                ah[mt][0] = AsHi[rb * 20 + pb16 + t];
                ah[mt][1] = AsHi[(rb + 8) * 20 + pb16 + t];
                ah[mt][2] = AsHi[rb * 20 + pb16 + t + 4];
                ah[mt][3] = AsHi[(rb + 8) * 20 + pb16 + t + 4];
                al[mt][0] = AsLo[rb * 20 + pb16 + t];
                al[mt][1] = AsLo[(rb + 8) * 20 + pb16 + t];
                al[mt][2] = AsLo[rb * 20 + pb16 + t + 4];
                al[mt][3] = AsLo[(rb + 8) * 20 + pb16 + t + 4];
            }
#pragma unroll
            for (int nt = 0; nt < 4; nt++) {
                int ncol = wn * 32 + nt * 8 + g;
                unsigned bh[2] = { WsHi[ncol * 68 + P0h + t], WsHi[ncol * 68 + P0h + t + 4] };
                unsigned bl[2] = { WsLo[ncol * 68 + P0h + t], WsLo[ncol * 68 + P0h + t + 4] };
#pragma unroll
                for (int mt = 0; mt < 2; mt++) {
                    mma16(acc[mt][nt], ah[mt], bh);
                    mma16(acc[mt][nt], al[mt], bh);
                    mma16(acc[mt][nt], ah[mt], bl);
                }
            }
        }
    }
#pragma unroll
    for (int mt = 0; mt < 2; mt++) {
#pragma unroll
        for (int nt = 0; nt < 4; nt++) {
            int c = z * 64 + wn * 32 + nt * 8 + 2 * t;
            float bx = bb[c], by = bb[c + 1];
            int r = r0 + wm * 32 + mt * 16 + g;
            *(float2*)&C[(size_t)r * HID + c] = make_float2(acc[mt][nt][0] + bx, acc[mt][nt][1] + by);
            *(float2*)&C[(size_t)(r + 8) * HID + c] = make_float2(acc[mt][nt][2] + bx, acc[mt][nt][3] + by);
        }
    }
}

// ================= edge GEMM (sorted), split-bf16; 1-D grid with z-paired adjacent blocks ====
__global__ __launch_bounds__(256, 3) void gemm_tc_edge(
    const float* __restrict__ A, const float* __restrict__ foldE, float* __restrict__ foldOut,
    const unsigned* __restrict__ Wp, const float* __restrict__ bias,
    float* __restrict__ C,
    const float* __restrict__ Dx, const float* __restrict__ Ex, const float* __restrict__ Bx,
    int doStats, int permA, int permF, int writeC, int writeFold) {
    extern __shared__ unsigned smu[];
    unsigned* AsHi = smu + AHI;
    unsigned* AsLo = smu + ALO;
    unsigned* WsHi = smu + WHI;
    unsigned* WsLo = smu + WLO;
    float* tile = (float*)smu;           // overlay 128x68 after mainloop
    int* sidx = (int*)(smu + OPW);
    int* didx = sidx + 128;
    int* pidx = didx + 128;

    int tid = threadIdx.x, lane = tid & 31, wid = tid >> 5;
    int wm = wid & 3, wn = wid >> 2, g = lane >> 2, t = lane & 3;
    // z-pairing: adjacent block ids share the same edge tile (L2 reuse of A/foldE reads)
    int bx = blockIdx.x >> 1;
    int z = blockIdx.x & 1;
    int r0 = bx * 128;
    int arow = tid >> 1, acb = (tid & 1) * 16, pb = (tid & 1) * 8;

    if (tid < 128) {
        sidx[tid] = g_src2[r0 + tid];
        didx[tid] = g_dst2[r0 + tid];
        pidx[tid] = g_perm[r0 + tid];
    }
    {
        int nloc = tid >> 2, kb = (tid & 3) * 16;
        const unsigned* WHg = Wp + (size_t)(z * 64 + nloc) * 64 + kb;
        const unsigned* WLg = WHg + 8192;
#pragma unroll
        for (int q = 0; q < 4; q++) {
            *(uint4*)&WsHi[nloc * 68 + kb + q * 4] = *(const uint4*)&WHg[q * 4];
            *(uint4*)&WsLo[nloc * 68 + kb + q * 4] = *(const uint4*)&WLg[q * 4];
        }
    }
    __syncthreads();

    float acc[2][4][4];
#pragma unroll
    for (int i = 0; i < 2; i++)
#pragma unroll
        for (int j = 0; j < 4; j++)
#pragma unroll
            for (int q = 0; q < 4; q++) acc[i][j][q] = 0.f;

    int doFold = (foldE != nullptr);
    int aIdx = permA ? pidx[arow] : (r0 + arow);
    int fIdx = permF ? pidx[arow] : (r0 + arow);
    int wF = writeFold && (z == 0);

    for (int k0 = 0; k0 < 128; k0 += 32) {
        if (k0) __syncthreads();
        float vals[16];
#pragma unroll
        for (int q = 0; q < 4; q++) {
            int kc = k0 + acb + q * 4;
            float4 av = *(const float4*)&A[(size_t)aIdx * HID + kc];
            if (doFold) {
                float4 ev = *(const float4*)&foldE[(size_t)fIdx * HID + kc];
                float4 sc = *(const float4*)&g_scE[kc];
                float4 sh = *(const float4*)&g_shE[kc];
                av.x = fmaxf(av.x * sc.x + sh.x, 0.f) + ev.x;
                av.y = fmaxf(av.y * sc.y + sh.y, 0.f) + ev.y;
                av.z = fmaxf(av.z * sc.z + sh.z, 0.f) + ev.z;
                av.w = fmaxf(av.w * sc.w + sh.w, 0.f) + ev.w;
                if (wF) *(float4*)&foldOut[(size_t)(r0 + arow) * HID + kc] = av;
            }
            vals[q * 4 + 0] = av.x; vals[q * 4 + 1] = av.y;
            vals[q * 4 + 2] = av.z; vals[q * 4 + 3] = av.w;
        }
#pragma unroll
        for (int j = 0; j < 8; j++) {
            unsigned h, l2;
            packpair(vals[2 * j], vals[2 * j + 1], h, l2);
            AsHi[arow * 20 + pb + j] = h;
            AsLo[arow * 20 + pb + j] = l2;
        }
        __syncthreads();
#pragma unroll
        for (int hh = 0; hh < 2; hh++) {
            int pb16 = hh * 8;
            int P0h = (k0 >> 1) + pb16;
            unsigned ah[2][4], al[2][4];
#pragma unroll
            for (int mt = 0; mt < 2; mt++) {
                int rb = wm * 32 + mt * 16 + g;
                ah[mt][0] = AsHi[rb * 20 + pb16 + t];
                ah[mt][1] = AsHi[(rb + 8) * 20 + pb16 + t];
                ah[mt][2] = AsHi[rb * 20 + pb16 + t + 4];
                ah[mt][3] = AsHi[(rb + 8) * 20 + pb16 + t + 4];
                al[mt][0] = AsLo[rb * 20 + pb16 + t];
                al[mt][1] = AsLo[(rb + 8) * 20 + pb16 + t];
                al[mt][2] = AsLo[rb * 20 + pb16 + t + 4];
                al[mt][3] = AsLo[(rb + 8) * 20 + pb16 + t + 4];
            }
#pragma unroll
            for (int nt = 0; nt < 4; nt++) {
                int ncol = wn * 32 + nt * 8 + g;
                unsigned bh[2] = { WsHi[ncol * 68 + P0h + t], WsHi[ncol * 68 + P0h + t + 4] };
                unsigned bl[2] = { WsLo[ncol * 68 + P0h + t], WsLo[ncol * 68 + P0h + t + 4] };
#pragma unroll
                for (int mt = 0; mt < 2; mt++) {
                    mma16(acc[mt][nt], ah[mt], bh);
                    mma16(acc[mt][nt], al[mt], bh);
                    mma16(acc[mt][nt], ah[mt], bl);
                }
            }
        }
    }
    __syncthreads();
#pragma unroll
    for (int mt = 0; mt < 2; mt++) {
#pragma unroll
        for (int nt = 0; nt < 4; nt++) {
            int cc = wn * 32 + nt * 8 + 2 * t;
            int r = wm * 32 + mt * 16 + g;
            tile[r * 68 + cc] = acc[mt][nt][0];
            tile[r * 68 + cc + 1] = acc[mt][nt][1];
            tile[(r + 8) * 68 + cc] = acc[mt][nt][2];
            tile[(r + 8) * 68 + cc + 1] = acc[mt][nt][3];
        }
    }
    __syncthreads();
    {
        int c4l = (tid & 15) * 4;
        int c4g = z * 64 + c4l;
        int chunk = tid >> 4;
        float4 bcv = *(const float4*)&bias[c4g];
        float4 s1v = make_float4(0.f, 0.f, 0.f, 0.f);
        float4 s2v = make_float4(0.f, 0.f, 0.f, 0.f);
        float4 accN = make_float4(0.f, 0.f, 0.f, 0.f);
        float4 accD = make_float4(0.f, 0.f, 0.f, 0.f);
        int curd = didx[chunk * 8];
#pragma unroll
        for (int rr = 0; rr < 8; rr++) {
            int r = chunk * 8 + rr;
            int d = didx[r], s = sidx[r];
            if (d != curd) {
                red4(&g_num[(size_t)curd * HID + c4g], accN);
                red4(&g_den[(size_t)curd * HID + c4g], accD);
                accN = make_float4(0.f, 0.f, 0.f, 0.f);
                accD = make_float4(0.f, 0.f, 0.f, 0.f);
                curd = d;
            }
            float4 tv = *(float4*)&tile[r * 68 + c4l];
            float4 dx = *(const float4*)&Dx[(size_t)d * HID + c4g];
            float4 ex = *(const float4*)&Ex[(size_t)s * HID + c4g];
            float4 bx = *(const float4*)&Bx[(size_t)s * HID + c4g];
            float4 v;
            v.x = tv.x + bcv.x + dx.x + ex.x;
            v.y = tv.y + bcv.y + dx.y + ex.y;
            v.z = tv.z + bcv.z + dx.z + ex.z;
            v.w = tv.w + bcv.w + dx.w + ex.w;
            if (writeC) *(float4*)&C[(size_t)(r0 + r) * HID + c4g] = v;
            float4 sg;
            sg.x = 1.f / (1.f + __expf(-v.x));
            sg.y = 1.f / (1.f + __expf(-v.y));
            sg.z = 1.f / (1.f + __expf(-v.z));
            sg.w = 1.f / (1.f + __expf(-v.w));
            accN.x += sg.x * bx.x; accN.y += sg.y * bx.y;
            accN.z += sg.z * bx.z; accN.w += sg.w * bx.w;
            accD.x += sg.x; accD.y += sg.y; accD.z += sg.z; accD.w += sg.w;
            s1v.x += v.x; s1v.y += v.y; s1v.z += v.z; s1v.w += v.w;
            s2v.x += v.x * v.x; s2v.y += v.y * v.y; s2v.z += v.z * v.z; s2v.w += v.w * v.w;
        }
        red4(&g_num[(size_t)curd * HID + c4g], accN);
        red4(&g_den[(size_t)curd * HID + c4g], accD);
        if (doStats) {
            red4(&g_part[bx * 256 + c4g], s1v);
            red4(&g_part[bx * 256 + 128 + c4g], s2v);
        }
    }
}

// ---------------- h_new = Ax + num/(den+eps) fused with BN partials ----------------
__global__ void node_hnew_stats_kernel() {
    int c = threadIdx.x;
    float s = 0.f, ss = 0.f;
    for (int r = blockIdx.x; r < NND; r += gridDim.x) {
        int i = r * HID + c;
        float v = g_Ax[i] + g_num[i] / (g_den[i] + 1e-6f);
        g_Ax[i] = v;
        s += v; ss += v * v;
    }
    g_part[blockIdx.x * 256 + c] = s;
    g_part[blockIdx.x * 256 + 128 + c] = ss;
}

// ---------------- BN finalize ----------------
__global__ void bn_finalize2(int G, float invM, const float* __restrict__ gamma,
                             const float* __restrict__ beta,
                             float* __restrict__ scale, float* __restrict__ shift) {
    int c = blockIdx.x;
    int tid = threadIdx.x;
    double s = 0.0, ss = 0.0;
    for (int gi = tid; gi < G; gi += 256) {
        s  += (double)g_part[gi * 256 + c];
        ss += (double)g_part[gi * 256 + 128 + c];
    }
    __shared__ double rs[256], rss[256];
    rs[tid] = s; rss[tid] = ss;
    __syncthreads();
    for (int o = 128; o > 0; o >>= 1) {
        if (tid < o) { rs[tid] += rs[tid + o]; rss[tid] += rss[tid + o]; }
        __syncthreads();
    }
    if (tid == 0) {
        double mu = rs[0] * (double)invM;
        double var = rss[0] * (double)invM - mu * mu;
        float inv = rsqrtf((float)var + 1e-5f);
        float scv = gamma[c] * inv;
        scale[c] = scv;
        shift[c] = beta[c] - (float)mu * scv;
    }
}

// ---------------- dense attention: 256 threads, 2 threads per query row ----------------
__global__ void attn_kernel(const float* __restrict__ q, const float* __restrict__ k,
                            const float* __restrict__ v, const float* __restrict__ sph,
                            float* __restrict__ o) {
    extern __shared__ float smf[];
    float* ks = smf;                    // [128][36]; retired after QK -> pacc/mxred/smred
    float* vs = smf + 128 * 36;         // [128][36]
    float* ps = smf + 2 * 128 * 36;     // [128][133]
    float* pacc = ks;                   // 32*128 floats (overlay)
    float* mxred = ks + 4096;           // 256
    float* smred = ks + 4352;           // 256
    int head = blockIdx.x, b = blockIdx.y;
    int tid = threadIdx.x;
    int s = tid & 127, p = tid >> 7;    // p = half selector
    int nodebase = (b * SEQ + s) * HID + head * 32;
    float qr[32];
#pragma unroll
    for (int d4 = 0; d4 < 8; d4++) {
        float4 tq = *(const float4*)&q[nodebase + d4 * 4];
        qr[d4 * 4] = tq.x; qr[d4 * 4 + 1] = tq.y; qr[d4 * 4 + 2] = tq.z; qr[d4 * 4 + 3] = tq.w;
        if (p == 0)
            *(float4*)&ks[s * 36 + d4 * 4] = *(const float4*)&k[nodebase + d4 * 4];
        else
            *(float4*)&vs[s * 36 + d4 * 4] = *(const float4*)&v[nodebase + d4 * 4];
    }
    __syncthreads();
    const float isd = 0.17677669529663687f;
    int t0 = p * 64;
    for (int t = t0; t < t0 + 64; t++) {
        float acc = 0.f;
#pragma unroll
        for (int d4 = 0; d4 < 8; d4++) {
            float4 kk = *(float4*)&ks[t * 36 + d4 * 4];
            acc += qr[d4 * 4] * kk.x + qr[d4 * 4 + 1] * kk.y +
                   qr[d4 * 4 + 2] * kk.z + qr[d4 * 4 + 3] * kk.w;
        }
        ps[s * 133 + t] = acc * isd;
    }
    __syncthreads();
    const float* sb = sph + b * SEQ * SEQ;
    for (int i = tid; i < SEQ * SEQ; i += 256) {
        int s2 = i >> 7, t2 = i & 127;
        ps[s2 * 133 + t2] *= sb[i];
    }
    __syncthreads();
    // half-range max (ks region retired; overlay is safe after this barrier)
    float mx = -1e30f;
    for (int t = t0; t < t0 + 64; t++) mx = fmaxf(mx, ps[s * 133 + t]);
    mxred[p * 128 + s] = mx;
    __syncthreads();
    float gmx = fmaxf(mxred[s], mxred[128 + s]);
    float sum = 0.f;
    for (int t = t0; t < t0 + 64; t++) {
        float e = __expf(ps[s * 133 + t] - gmx);
        ps[s * 133 + t] = e;
        sum += e;
    }
    smred[p * 128 + s] = sum;
    __syncthreads();
    float inv = 1.f / (smred[s] + smred[128 + s]);
    float acc[32];
#pragma unroll
    for (int d = 0; d < 32; d++) acc[d] = 0.f;
    for (int t = t0; t < t0 + 64; t++) {
        float pw = ps[s * 133 + t];
#pragma unroll
        for (int d4 = 0; d4 < 8; d4++) {
            float4 vvv = *(float4*)&vs[t * 36 + d4 * 4];
            acc[d4 * 4] += pw * vvv.x; acc[d4 * 4 + 1] += pw * vvv.y;
            acc[d4 * 4 + 2] += pw * vvv.z; acc[d4 * 4 + 3] += pw * vvv.w;
        }
    }
    if (p == 1) {
#pragma unroll
        for (int d = 0; d < 32; d++) pacc[d * 128 + s] = acc[d];
    }
    __syncthreads();
    if (p == 0) {
#pragma unroll
        for (int d4 = 0; d4 < 8; d4++) {
            float4 t4;
            t4.x = (acc[d4 * 4] + pacc[(d4 * 4) * 128 + s]) * inv;
            t4.y = (acc[d4 * 4 + 1] + pacc[(d4 * 4 + 1) * 128 + s]) * inv;
            t4.z = (acc[d4 * 4 + 2] + pacc[(d4 * 4 + 2) * 128 + s]) * inv;
            t4.w = (acc[d4 * 4 + 3] + pacc[(d4 * 4 + 3) * 128 + s]) * inv;
            *(float4*)&o[nodebase + d4 * 4] = t4;
        }
    }
}

// ---------------- mean pool + tiny MLP ----------------
__global__ void pool_kernel() {
    int b = blockIdx.x, c = threadIdx.x;
    float s = 0.f;
    for (int i = 0; i < SEQ; i++) s += g_h[(b * SEQ + i) * HID + c];
    g_pool[b * HID + c] = s * (1.f / 128.f);
}
__global__ void mlp_kernel(const float* __restrict__ in, const float* __restrict__ W,
                           const float* __restrict__ bias, float* __restrict__ out,
                           int K, int Ncol, int doRelu) {
    int r = blockIdx.x;
    __shared__ float xs[128];
    if ((int)threadIdx.x < K) xs[threadIdx.x] = in[r * K + threadIdx.x];
    __syncthreads();
    int c = threadIdx.x;
    if (c < Ncol) {
        float acc = bias[c];
        for (int k = 0; k < K; k++) acc += xs[k] * W[k * Ncol + c];
        if (doRelu) acc = fmaxf(acc, 0.f);
        out[r * Ncol + c] = acc;
    }
}

// ---------------- launch ----------------
extern "C" void kernel_launch(void* const* d_in, const int* in_sizes, int n_in,
                              void* d_out, int out_size) {
    const float* x        = (const float*)d_in[0];
    const float* pe       = (const float*)d_in[1];
    const float* edge_attr= (const float*)d_in[2];
    const float* sph      = (const float*)d_in[3];
    const float* node_w   = (const float*)d_in[4];
    const float* node_b   = (const float*)d_in[5];
    const float* pe_w     = (const float*)d_in[6];
    const float* pe_b     = (const float*)d_in[7];
    const float* Aw       = (const float*)d_in[8];
    const float* Ab       = (const float*)d_in[9];
    const float* Bw       = (const float*)d_in[10];
    const float* Bb       = (const float*)d_in[11];
    const float* Cw       = (const float*)d_in[12];
    const float* Cb       = (const float*)d_in[13];
    const float* Dw       = (const float*)d_in[14];
    const float* Db       = (const float*)d_in[15];
    const float* Ew       = (const float*)d_in[16];
    const float* Eb       = (const float*)d_in[17];
    const float* bnxg     = (const float*)d_in[18];
    const float* bnxb     = (const float*)d_in[19];
    const float* bneg     = (const float*)d_in[20];
    const float* bneb     = (const float*)d_in[21];
    const float* attw     = (const float*)d_in[22];
    const float* attb     = (const float*)d_in[23];
    const float* m1w      = (const float*)d_in[24];
    const float* m1b      = (const float*)d_in[25];
    const float* m2w      = (const float*)d_in[26];
    const float* m2b      = (const float*)d_in[27];
    const float* m3w      = (const float*)d_in[28];
    const float* m3b      = (const float*)d_in[29];
    const int*   ei       = (const int*)d_in[30];
    float* out = (float*)d_out;

    float *p_h, *p_eA, *p_eB, *p_eijA, *p_eijB, *p_Ax, *p_Bx, *p_Dx, *p_Ex, *p_num, *p_den;
    float *p_scN, *p_shN, *p_scE, *p_shE, *p_pool, *p_t1, *p_t2;
    unsigned* p_Wpack;
    cudaGetSymbolAddress((void**)&p_h,    g_h);
    cudaGetSymbolAddress((void**)&p_eA,   g_eA);
    cudaGetSymbolAddress((void**)&p_eB,   g_eB);
    cudaGetSymbolAddress((void**)&p_eijA, g_eijA);
    cudaGetSymbolAddress((void**)&p_eijB, g_eijB);
    cudaGetSymbolAddress((void**)&p_Ax,   g_Ax);
    cudaGetSymbolAddress((void**)&p_Bx,   g_Bx);
    cudaGetSymbolAddress((void**)&p_Dx,   g_Dx);
    cudaGetSymbolAddress((void**)&p_Ex,   g_Ex);
    cudaGetSymbolAddress((void**)&p_num,  g_num);
    cudaGetSymbolAddress((void**)&p_den,  g_den);
    cudaGetSymbolAddress((void**)&p_scN,  g_scN);
    cudaGetSymbolAddress((void**)&p_shN,  g_shN);
    cudaGetSymbolAddress((void**)&p_scE,  g_scE);
    cudaGetSymbolAddress((void**)&p_shE,  g_shE);
    cudaGetSymbolAddress((void**)&p_pool, g_pool);
    cudaGetSymbolAddress((void**)&p_t1,   g_t1);
    cudaGetSymbolAddress((void**)&p_t2,   g_t2);
    cudaGetSymbolAddress((void**)&p_Wpack, g_Wpack);

    float* eij_bufs[2] = { p_eijA, p_eijB };
    float* e_bufs[2]   = { p_eA, p_eB };

    const int* src = ei;
    const int* dst = ei + NE;
    const int ATTN_SMEM = (2 * 128 * 36 + 128 * 133) * 4;
    const int PLAIN_SMEM = OPW * 4;
    const int EDGE_SMEM = (OPW + 384) * 4;
    cudaFuncSetAttribute(attn_kernel, cudaFuncAttributeMaxDynamicSharedMemorySize, ATTN_SMEM);
    cudaFuncSetAttribute(gemm_tc, cudaFuncAttributeMaxDynamicSharedMemorySize, PLAIN_SMEM);
    cudaFuncSetAttribute(gemm_tc_edge, cudaFuncAttributeMaxDynamicSharedMemorySize, EDGE_SMEM);

    init_kernel<<<2048, 256>>>();
    pack_w_kernel<<<24, 256>>>(Aw, Bw, Dw, Ew, Cw, attw);
    hist_kernel<<<NE / 256, 256>>>(dst);
    scan_kernel<<<1, 1024>>>();
    scatter_kernel<<<NE / 256, 256>>>(src, dst);
    input_proj_kernel<<<NND, 128>>>(x, pe, node_w, node_b, pe_w, pe_b);

    for (int l = 0; l < NL; l++) {
        if (l > 0) zero_nd_kernel<<<2048, 256>>>();
        dim3 g4(NND / 128, 4, 2);
        gemm_tc<<<g4, 256, PLAIN_SMEM>>>(p_h, nullptr, 0,
            p_Wpack + (l * 5 + 0) * 16384, p_Wpack + (l * 5 + 1) * 16384,
            p_Wpack + (l * 5 + 2) * 16384, p_Wpack + (l * 5 + 3) * 16384,
            Ab + l * HID, Bb + l * HID, Db + l * HID, Eb + l * HID,
            p_Ax, p_Bx, p_Dx, p_Ex);
        const float* eA    = (l == 0) ? edge_attr : eij_bufs[(l - 1) & 1];
        float* eij_out     = eij_bufs[l & 1];
        const float* foldE = (l == 0) ? nullptr : ((l == 1) ? edge_attr : e_bufs[(l - 1) & 1]);
        float* fold_out    = e_bufs[l & 1];
        int permA = (l == 0) ? 1 : 0;
        int permF = (l == 1) ? 1 : 0;
        int last = (l == NL - 1);
        gemm_tc_edge<<<NE / 64, 256, EDGE_SMEM>>>(
            eA, foldE, fold_out, p_Wpack + (l * 5 + 4) * 16384, Cb + l * HID, eij_out,
            p_Dx, p_Ex, p_Bx, last ? 0 : 1, permA, permF,
            last ? 0 : 1, last ? 0 : 1);
        if (!last)
            bn_finalize2<<<HID, 256>>>(2048, 1.f / NE, bneg + l * HID, bneb + l * HID, p_scE, p_shE);
        node_hnew_stats_kernel<<<1024, 128>>>();
        bn_finalize2<<<HID, 256>>>(1024, 1.f / NND, bnxg + l * HID, bnxb + l * HID, p_scN, p_shN);
        dim3 g3(NND / 128, 3, 2);
        gemm_tc<<<g3, 256, PLAIN_SMEM>>>(p_Ax, p_h, 1,
            p_Wpack + 20 * 16384, p_Wpack + 21 * 16384,
            p_Wpack + 22 * 16384, p_Wpack + 22 * 16384,
            attb + 0 * HID, attb + 1 * HID, attb + 2 * HID, attb + 2 * HID,
            p_den, p_Bx, p_Dx, p_Dx);
        dim3 ag(4, BATCH);
        attn_kernel<<<ag, 256, ATTN_SMEM>>>(p_den, p_Bx, p_Dx, sph, p_Ex);
        dim3 g1(NND / 128, 1, 2);
        gemm_tc<<<g1, 256, PLAIN_SMEM>>>(p_Ex, nullptr, 0,
            p_Wpack + 23 * 16384, p_Wpack + 23 * 16384,
            p_Wpack + 23 * 16384, p_Wpack + 23 * 16384,
            attb + 3 * HID, attb + 3 * HID, attb + 3 * HID, attb + 3 * HID,
            p_h, p_h, p_h, p_h);
    }
    pool_kernel<<<BATCH, 128>>>();
    mlp_kernel<<<BATCH, 128>>>(p_pool, m1w, m1b, p_t1, 128, 64, 1);
    mlp_kernel<<<BATCH, 128>>>(p_t1, m2w, m2b, p_t2, 64, 32, 1);
    mlp_kernel<<<BATCH, 128>>>(p_t2, m3w, m3b, out, 32, 10, 0);
}

// round 14
// speedup vs baseline: 1.2043x; 1.0167x over previous
#include <cuda_runtime.h>
#include <cuda_bf16.h>
#include <cstdint>

#define NND 16384
#define NE  262144
#define HID 128
#define BATCH 128
#define SEQ 128
#define NL 4
#define WSZ (HID*HID)

// smem word offsets
#define AHI 0        // 128 x 20 pairs
#define ALO 2560
#define WHI 5120     // 64 x 68 pairs
#define WLO 9472
#define OPW 13824
// edge overlays: tile = words 0..8703, sred = 8704..10751, idx at OPW

// ---------------- scratch ----------------
__device__ float g_h[NND * HID];
__device__ float g_eA[NE * HID];
__device__ float g_eB[NE * HID];
__device__ float g_eijA[NE * HID];
__device__ float g_eijB[NE * HID];
__device__ float g_Ax[NND * HID];
__device__ float g_Bx[NND * HID];
__device__ float g_Dx[NND * HID];
__device__ float g_Ex[NND * HID];
__device__ float g_num[NND * HID];
__device__ float g_den[NND * HID];
__device__ float g_stats[512];   // [0:128) edge s1, [128:256) edge s2, [256:384) node s, [384:512) node ss
__device__ float g_scN[HID], g_shN[HID], g_scE[HID], g_shE[HID];
__device__ float g_pool[BATCH * HID];
__device__ float g_t1[BATCH * 64];
__device__ float g_t2[BATCH * 32];
__device__ unsigned g_Wpack[24 * 16384];
// edge sort
__device__ int g_cnt[NND];
__device__ int g_src2[NE];
__device__ int g_dst2[NE];
__device__ int g_perm[NE];

// ---------------- helpers ----------------
__device__ __forceinline__ void packpair(float f0, float f1, unsigned& hi, unsigned& lo) {
    __nv_bfloat162 h = __floats2bfloat162_rn(f0, f1);
    float r0 = f0 - __bfloat162float(h.x);
    float r1 = f1 - __bfloat162float(h.y);
    __nv_bfloat162 l2 = __floats2bfloat162_rn(r0, r1);
    hi = *reinterpret_cast<unsigned*>(&h);
    lo = *reinterpret_cast<unsigned*>(&l2);
}
__device__ __forceinline__ void mma16(float* d, const unsigned* a, const unsigned* b) {
    asm volatile("mma.sync.aligned.m16n8k16.row.col.f32.bf16.bf16.f32 "
        "{%0,%1,%2,%3}, {%4,%5,%6,%7}, {%8,%9}, {%0,%1,%2,%3};"
        : "+f"(d[0]), "+f"(d[1]), "+f"(d[2]), "+f"(d[3])
        : "r"(a[0]), "r"(a[1]), "r"(a[2]), "r"(a[3]), "r"(b[0]), "r"(b[1]));
}
__device__ __forceinline__ void red4(float* p, float4 v) {
    asm volatile("red.global.add.v4.f32 [%0], {%1,%2,%3,%4};"
        :: "l"(p), "f"(v.x), "f"(v.y), "f"(v.z), "f"(v.w) : "memory");
}
__device__ __forceinline__ void red1(float* p, float v) {
    asm volatile("red.global.add.f32 [%0], %1;" :: "l"(p), "f"(v) : "memory");
}

// ---------------- weight pre-split ----------------
__global__ void pack_w_kernel(const float* __restrict__ Aw, const float* __restrict__ Bw,
                              const float* __restrict__ Dw, const float* __restrict__ Ew,
                              const float* __restrict__ Cw, const float* __restrict__ attw) {
    int m = blockIdx.x;
    const float* src;
    if (m < 20) {
        int l = m / 5, s = m % 5;
        src = ((s == 0) ? Aw : (s == 1) ? Bw : (s == 2) ? Dw : (s == 3) ? Ew : Cw) + l * WSZ;
    } else {
        src = attw + (m - 20) * WSZ;
    }
    unsigned* hi = g_Wpack + m * 16384;
    unsigned* lo = hi + 8192;
    for (int i = threadIdx.x; i < 8192; i += 256) {
        int n = i >> 6, kp = i & 63;
        float f0 = src[(2 * kp) * HID + n];
        float f1 = src[(2 * kp + 1) * HID + n];
        unsigned h, l2;
        packpair(f0, f1, h, l2);
        hi[i] = h;
        lo[i] = l2;
    }
}

// ---------------- init: zero cnt + stats ----------------
__global__ void init_kernel() {
    int i = blockIdx.x * 256 + threadIdx.x;
    if (i < NND / 4) ((int4*)g_cnt)[i] = make_int4(0, 0, 0, 0);
    if (i < 512) g_stats[i] = 0.f;
}

// ---------------- edge counting sort ----------------
__global__ void hist_kernel(const int* __restrict__ dst) {
    int i = blockIdx.x * blockDim.x + threadIdx.x;
    if (i < NE) atomicAdd(&g_cnt[dst[i]], 1);
}
__global__ __launch_bounds__(1024) void scan_kernel() {
    __shared__ int ssum[1024];
    int tid = threadIdx.x;
    int base = tid * 16;
    int loc[16]; int s = 0;
#pragma unroll
    for (int i = 0; i < 16; i++) { loc[i] = s; s += g_cnt[base + i]; }
    ssum[tid] = s;
    __syncthreads();
    for (int off = 1; off < 1024; off <<= 1) {
        int v = (tid >= off) ? ssum[tid - off] : 0;
        __syncthreads();
        ssum[tid] += v;
        __syncthreads();
    }
    int pre = (tid == 0) ? 0 : ssum[tid - 1];
#pragma unroll
    for (int i = 0; i < 16; i++) g_cnt[base + i] = pre + loc[i];
}
__global__ void scatter_kernel(const int* __restrict__ src, const int* __restrict__ dst) {
    int i = blockIdx.x * blockDim.x + threadIdx.x;
    if (i >= NE) return;
    int d = dst[i];
    int pos = atomicAdd(&g_cnt[d], 1);
    g_perm[pos] = i;
    g_src2[pos] = src[i];
    g_dst2[pos] = d;
}

// ---------------- input projection ----------------
__global__ void input_proj_kernel(const float* __restrict__ x, const float* __restrict__ pe,
                                  const float* __restrict__ nw, const float* __restrict__ nb,
                                  const float* __restrict__ pw, const float* __restrict__ pb) {
    int row = blockIdx.x;
    int c = threadIdx.x;
    __shared__ float xs[64];
    __shared__ float ps[16];
    if (c < 64) xs[c] = x[row * 64 + c];
    else if (c < 80) ps[c - 64] = pe[row * 16 + (c - 64)];
    __syncthreads();
    float acc;
    if (c < 112) {
        acc = nb[c];
#pragma unroll
        for (int k = 0; k < 64; k++) acc += xs[k] * nw[k * 112 + c];
    } else {
        int cc = c - 112;
        acc = pb[cc];
#pragma unroll
        for (int k = 0; k < 16; k++) acc += ps[k] * pw[k * 16 + cc];
    }
    g_h[row * HID + c] = acc;
}

// ================= split-bf16 GEMM, tile 128x64 (z-split N), multi-W via blockIdx.y ==========
// zeroND: y==0 blocks zero g_num region, y==1 -> g_den, (y==3,x==0,z==0) -> g_stats
__global__ __launch_bounds__(256, 3) void gemm_tc(
    const float* __restrict__ A, const float* __restrict__ foldE, int doFold, int zeroND,
    const unsigned* __restrict__ Wp0, const unsigned* __restrict__ Wp1,
    const unsigned* __restrict__ Wp2, const unsigned* __restrict__ Wp3,
    const float* __restrict__ b0, const float* __restrict__ b1,
    const float* __restrict__ b2, const float* __restrict__ b3,
    float* __restrict__ C0, float* __restrict__ C1,
    float* __restrict__ C2, float* __restrict__ C3) {
    int y = blockIdx.y, z = blockIdx.z;
    const unsigned* Wp = (y == 0) ? Wp0 : (y == 1) ? Wp1 : (y == 2) ? Wp2 : Wp3;
    const float* bb = (y == 0) ? b0 : (y == 1) ? b1 : (y == 2) ? b2 : b3;
    float* C = (y == 0) ? C0 : (y == 1) ? C1 : (y == 2) ? C2 : C3;

    extern __shared__ unsigned smu[];
    unsigned* AsHi = smu + AHI;
    unsigned* AsLo = smu + ALO;
    unsigned* WsHi = smu + WHI;
    unsigned* WsLo = smu + WLO;

    int tid = threadIdx.x, lane = tid & 31, wid = tid >> 5;
    int wm = wid & 3, wn = wid >> 2, g = lane >> 2, t = lane & 3;
    int r0 = blockIdx.x * 128;
    int arow = tid >> 1, acb = (tid & 1) * 16, pb = (tid & 1) * 8;

    // fused zeroing (hidden under GEMM)
    if (zeroND) {
        if (y < 2) {
            float* dstp = (y == 0) ? g_num : g_den;
            float4 zz = make_float4(0.f, 0.f, 0.f, 0.f);
#pragma unroll
            for (int i = 0; i < 8; i++) {
                int slot = i * 256 + tid;          // coalesced
                int row = slot >> 4, c4 = slot & 15;
                *(float4*)&dstp[(size_t)(r0 + row) * HID + z * 64 + c4 * 4] = zz;
            }
        } else if (y == 3 && blockIdx.x == 0 && z == 0) {
            if (tid < 256) { g_stats[tid] = 0.f; g_stats[256 + tid] = 0.f; }
        }
    }

    {
        int nloc = tid >> 2, kb = (tid & 3) * 16;
        const unsigned* WHg = Wp + (size_t)(z * 64 + nloc) * 64 + kb;
        const unsigned* WLg = WHg + 8192;
#pragma unroll
        for (int q = 0; q < 4; q++) {
            *(uint4*)&WsHi[nloc * 68 + kb + q * 4] = *(const uint4*)&WHg[q * 4];
            *(uint4*)&WsLo[nloc * 68 + kb + q * 4] = *(const uint4*)&WLg[q * 4];
        }
    }

    float acc[2][4][4];
#pragma unroll
    for (int i = 0; i < 2; i++)
#pragma unroll
        for (int j = 0; j < 4; j++)
#pragma unroll
            for (int q = 0; q < 4; q++) acc[i][j][q] = 0.f;

    for (int k0 = 0; k0 < 128; k0 += 32) {
        __syncthreads();
        float vals[16];
#pragma unroll
        for (int q = 0; q < 4; q++) {
            int kc = k0 + acb + q * 4;
            float4 av = *(const float4*)&A[(size_t)(r0 + arow) * HID + kc];
            if (doFold) {
                float4 ev = *(const float4*)&foldE[(size_t)(r0 + arow) * HID + kc];
                float4 sc = *(const float4*)&g_scN[kc];
                float4 sh = *(const float4*)&g_shN[kc];
                av.x = fmaxf(av.x * sc.x + sh.x, 0.f) + ev.x;
                av.y = fmaxf(av.y * sc.y + sh.y, 0.f) + ev.y;
                av.z = fmaxf(av.z * sc.z + sh.z, 0.f) + ev.z;
                av.w = fmaxf(av.w * sc.w + sh.w, 0.f) + ev.w;
            }
            vals[q * 4 + 0] = av.x; vals[q * 4 + 1] = av.y;
            vals[q * 4 + 2] = av.z; vals[q * 4 + 3] = av.w;
        }
#pragma unroll
        for (int j = 0; j < 8; j++) {
            unsigned h, l2;
            packpair(vals[2 * j], vals[2 * j + 1], h, l2);
            AsHi[arow * 20 + pb + j] = h;
            AsLo[arow * 20 + pb + j] = l2;
        }
        __syncthreads();
#pragma unroll
        for (int hh = 0; hh < 2; hh++) {
            int pb16 = hh * 8;
            int P0h = (k0 >> 1) + pb16;
            unsigned ah[2][4], al[2][4];
#pragma unroll
            for (int mt = 0; mt < 2; mt++) {
                int rb = wm * 32 + mt * 16 + g;
                ah[mt][0] = AsHi[rb * 20 + pb16 + t];
                ah[mt][1] = AsHi[(rb + 8) * 20 + pb16 + t];
                ah[mt][2] = AsHi[rb * 20 + pb16 + t + 4];
                ah[mt][3] = AsHi[(rb + 8) * 20 + pb16 + t + 4];
                al[mt][0] = AsLo[rb * 20 + pb16 + t];
                al[mt][1] = AsLo[(rb + 8) * 20 + pb16 + t];
                al[mt][2] = AsLo[rb * 20 + pb16 + t + 4];
                al[mt][3] = AsLo[(rb + 8) * 20 + pb16 + t + 4];
            }
#pragma unroll
            for (int nt = 0; nt < 4; nt++) {
                int ncol = wn * 32 + nt * 8 + g;
                unsigned bh[2] = { WsHi[ncol * 68 + P0h + t], WsHi[ncol * 68 + P0h + t + 4] };
                unsigned bl[2] = { WsLo[ncol * 68 + P0h + t], WsLo[ncol * 68 + P0h + t + 4] };
#pragma unroll
                for (int mt = 0; mt < 2; mt++) {
                    mma16(acc[mt][nt], ah[mt], bh);
                    mma16(acc[mt][nt], al[mt], bh);
                    mma16(acc[mt][nt], ah[mt], bl);
                }
            }
        }
    }
#pragma unroll
    for (int mt = 0; mt < 2; mt++) {
#pragma unroll
        for (int nt = 0; nt < 4; nt++) {
            int c = z * 64 + wn * 32 + nt * 8 + 2 * t;
            float bx = bb[c], by = bb[c + 1];
            int r = r0 + wm * 32 + mt * 16 + g;
            *(float2*)&C[(size_t)r * HID + c] = make_float2(acc[mt][nt][0] + bx, acc[mt][nt][1] + by);
            *(float2*)&C[(size_t)(r + 8) * HID + c] = make_float2(acc[mt][nt][2] + bx, acc[mt][nt][3] + by);
        }
    }
}

// ================= edge GEMM (sorted), split-bf16; 1-D grid, z-paired; tiny-stats epilogue ===
__global__ __launch_bounds__(256, 3) void gemm_tc_edge(
    const float* __restrict__ A, const float* __restrict__ foldE, float* __restrict__ foldOut,
    const unsigned* __restrict__ Wp, const float* __restrict__ bias,
    float* __restrict__ C,
    const float* __restrict__ Dx, const float* __restrict__ Ex, const float* __restrict__ Bx,
    int doStats, int permA, int permF, int writeC, int writeFold) {
    extern __shared__ unsigned smu[];
    unsigned* AsHi = smu + AHI;
    unsigned* AsLo = smu + ALO;
    unsigned* WsHi = smu + WHI;
    unsigned* WsLo = smu + WLO;
    float* tile = (float*)smu;            // overlay 128x68 = words 0..8703
    float* sred = (float*)(smu + 8704);   // 2048 words: s1[1024], s2[1024]
    int* sidx = (int*)(smu + OPW);
    int* didx = sidx + 128;
    int* pidx = didx + 128;

    int tid = threadIdx.x, lane = tid & 31, wid = tid >> 5;
    int wm = wid & 3, wn = wid >> 2, g = lane >> 2, t = lane & 3;
    int bx = blockIdx.x >> 1;
    int z = blockIdx.x & 1;
    int r0 = bx * 128;
    int arow = tid >> 1, acb = (tid & 1) * 16, pb = (tid & 1) * 8;

    if (tid < 128) {
        sidx[tid] = g_src2[r0 + tid];
        didx[tid] = g_dst2[r0 + tid];
        pidx[tid] = g_perm[r0 + tid];
    }
    {
        int nloc = tid >> 2, kb = (tid & 3) * 16;
        const unsigned* WHg = Wp + (size_t)(z * 64 + nloc) * 64 + kb;
        const unsigned* WLg = WHg + 8192;
#pragma unroll
        for (int q = 0; q < 4; q++) {
            *(uint4*)&WsHi[nloc * 68 + kb + q * 4] = *(const uint4*)&WHg[q * 4];
            *(uint4*)&WsLo[nloc * 68 + kb + q * 4] = *(const uint4*)&WLg[q * 4];
        }
    }
    __syncthreads();

    float acc[2][4][4];
#pragma unroll
    for (int i = 0; i < 2; i++)
#pragma unroll
        for (int j = 0; j < 4; j++)
#pragma unroll
            for (int q = 0; q < 4; q++) acc[i][j][q] = 0.f;

    int doFold = (foldE != nullptr);
    int aIdx = permA ? pidx[arow] : (r0 + arow);
    int fIdx = permF ? pidx[arow] : (r0 + arow);
    int wF = writeFold && (z == 0);

    for (int k0 = 0; k0 < 128; k0 += 32) {
        if (k0) __syncthreads();
        float vals[16];
#pragma unroll
        for (int q = 0; q < 4; q++) {
            int kc = k0 + acb + q * 4;
            float4 av = *(const float4*)&A[(size_t)aIdx * HID + kc];
            if (doFold) {
                float4 ev = *(const float4*)&foldE[(size_t)fIdx * HID + kc];
                float4 sc = *(const float4*)&g_scE[kc];
                float4 sh = *(const float4*)&g_shE[kc];
                av.x = fmaxf(av.x * sc.x + sh.x, 0.f) + ev.x;
                av.y = fmaxf(av.y * sc.y + sh.y, 0.f) + ev.y;
                av.z = fmaxf(av.z * sc.z + sh.z, 0.f) + ev.z;
                av.w = fmaxf(av.w * sc.w + sh.w, 0.f) + ev.w;
                if (wF) *(float4*)&foldOut[(size_t)(r0 + arow) * HID + kc] = av;
            }
            vals[q * 4 + 0] = av.x; vals[q * 4 + 1] = av.y;
            vals[q * 4 + 2] = av.z; vals[q * 4 + 3] = av.w;
        }
#pragma unroll
        for (int j = 0; j < 8; j++) {
            unsigned h, l2;
            packpair(vals[2 * j], vals[2 * j + 1], h, l2);
            AsHi[arow * 20 + pb + j] = h;
            AsLo[arow * 20 + pb + j] = l2;
        }
        __syncthreads();
#pragma unroll
        for (int hh = 0; hh < 2; hh++) {
            int pb16 = hh * 8;
            int P0h = (k0 >> 1) + pb16;
            unsigned ah[2][4], al[2][4];
#pragma unroll
            for (int mt = 0; mt < 2; mt++) {
                int rb = wm * 32 + mt * 16 + g;
                ah[mt][0] = AsHi[rb * 20 + pb16 + t];
                ah[mt][1] = AsHi[(rb + 8) * 20 + pb16 + t];
                ah[mt][2] = AsHi[rb * 20 + pb16 + t + 4];
                ah[mt][3] = AsHi[(rb + 8) * 20 + pb16 + t + 4];
                al[mt][0] = AsLo[rb * 20 + pb16 + t];
                al[mt][1] = AsLo[(rb + 8) * 20 + pb16 + t];
                al[mt][2] = AsLo[rb * 20 + pb16 + t + 4];
                al[mt][3] = AsLo[(rb + 8) * 20 + pb16 + t + 4];
            }
#pragma unroll
            for (int nt = 0; nt < 4; nt++) {
                int ncol = wn * 32 + nt * 8 + g;
                unsigned bh[2] = { WsHi[ncol * 68 + P0h + t], WsHi[ncol * 68 + P0h + t + 4] };
                unsigned bl[2] = { WsLo[ncol * 68 + P0h + t], WsLo[ncol * 68 + P0h + t + 4] };
#pragma unroll
                for (int mt = 0; mt < 2; mt++) {
                    mma16(acc[mt][nt], ah[mt], bh);
                    mma16(acc[mt][nt], al[mt], bh);
                    mma16(acc[mt][nt], ah[mt], bl);
                }
            }
        }
    }
    __syncthreads();
#pragma unroll
    for (int mt = 0; mt < 2; mt++) {
#pragma unroll
        for (int nt = 0; nt < 4; nt++) {
            int cc = wn * 32 + nt * 8 + 2 * t;
            int r = wm * 32 + mt * 16 + g;
            tile[r * 68 + cc] = acc[mt][nt][0];
            tile[r * 68 + cc + 1] = acc[mt][nt][1];
            tile[(r + 8) * 68 + cc] = acc[mt][nt][2];
            tile[(r + 8) * 68 + cc + 1] = acc[mt][nt][3];
        }
    }
    __syncthreads();
    {
        int c4l = (tid & 15) * 4;
        int c4g = z * 64 + c4l;
        int chunk = tid >> 4;  // 0..15, 8 rows each
        float4 bcv = *(const float4*)&bias[c4g];
        float4 s1v = make_float4(0.f, 0.f, 0.f, 0.f);
        float4 s2v = make_float4(0.f, 0.f, 0.f, 0.f);
        float4 accN = make_float4(0.f, 0.f, 0.f, 0.f);
        float4 accD = make_float4(0.f, 0.f, 0.f, 0.f);
        int curd = didx[chunk * 8];
#pragma unroll
        for (int rr = 0; rr < 8; rr++) {
            int r = chunk * 8 + rr;
            int d = didx[r], s = sidx[r];
            if (d != curd) {
                red4(&g_num[(size_t)curd * HID + c4g], accN);
                red4(&g_den[(size_t)curd * HID + c4g], accD);
                accN = make_float4(0.f, 0.f, 0.f, 0.f);
                accD = make_float4(0.f, 0.f, 0.f, 0.f);
                curd = d;
            }
            float4 tv = *(float4*)&tile[r * 68 + c4l];
            float4 dx = *(const float4*)&Dx[(size_t)d * HID + c4g];
            float4 ex = *(const float4*)&Ex[(size_t)s * HID + c4g];
            float4 bx = *(const float4*)&Bx[(size_t)s * HID + c4g];
            float4 v;
            v.x = tv.x + bcv.x + dx.x + ex.x;
            v.y = tv.y + bcv.y + dx.y + ex.y;
            v.z = tv.z + bcv.z + dx.z + ex.z;
            v.w = tv.w + bcv.w + dx.w + ex.w;
            if (writeC) *(float4*)&C[(size_t)(r0 + r) * HID + c4g] = v;
            float4 sg;
            sg.x = 1.f / (1.f + __expf(-v.x));
            sg.y = 1.f / (1.f + __expf(-v.y));
            sg.z = 1.f / (1.f + __expf(-v.z));
            sg.w = 1.f / (1.f + __expf(-v.w));
            accN.x += sg.x * bx.x; accN.y += sg.y * bx.y;
            accN.z += sg.z * bx.z; accN.w += sg.w * bx.w;
            accD.x += sg.x; accD.y += sg.y; accD.z += sg.z; accD.w += sg.w;
            s1v.x += v.x; s1v.y += v.y; s1v.z += v.z; s1v.w += v.w;
            s2v.x += v.x * v.x; s2v.y += v.y * v.y; s2v.z += v.z * v.z; s2v.w += v.w * v.w;
        }
        red4(&g_num[(size_t)curd * HID + c4g], accN);
        red4(&g_den[(size_t)curd * HID + c4g], accD);
        if (doStats) {
            *(float4*)&sred[chunk * 64 + c4l] = s1v;
            *(float4*)&sred[1024 + chunk * 64 + c4l] = s2v;
        }
    }
    if (doStats) {
        __syncthreads();
        if (tid < 64) {
            float a = 0.f;
#pragma unroll
            for (int ch = 0; ch < 16; ch++) a += sred[ch * 64 + tid];
            red1(&g_stats[z * 64 + tid], a);
        } else if (tid < 128) {
            int c = tid - 64;
            float b2 = 0.f;
#pragma unroll
            for (int ch = 0; ch < 16; ch++) b2 += sred[1024 + ch * 64 + c];
            red1(&g_stats[128 + z * 64 + c], b2);
        }
    }
}

// ---------------- h_new = Ax + num/(den+eps), stats via red1 ----------------
__global__ void node_hnew_stats_kernel() {
    int c = threadIdx.x;
    float s = 0.f, ss = 0.f;
    for (int r = blockIdx.x; r < NND; r += gridDim.x) {
        int i = r * HID + c;
        float v = g_Ax[i] + g_num[i] / (g_den[i] + 1e-6f);
        g_Ax[i] = v;
        s += v; ss += v * v;
    }
    red1(&g_stats[256 + c], s);
    red1(&g_stats[384 + c], ss);
}

// ---------------- tiny BN finalize: 1 block, 128 threads ----------------
__global__ void bn_fin_kernel(int off, float invM, const float* __restrict__ gamma,
                              const float* __restrict__ beta,
                              float* __restrict__ scale, float* __restrict__ shift) {
    int c = threadIdx.x;
    double s = (double)g_stats[off + c];
    double ss = (double)g_stats[off + 128 + c];
    double mu = s * (double)invM;
    double var = ss * (double)invM - mu * mu;
    float inv = rsqrtf((float)var + 1e-5f);
    float scv = gamma[c] * inv;
    scale[c] = scv;
    shift[c] = beta[c] - (float)mu * scv;
}

// ---------------- dense attention: 256 threads, 2 threads per query row ----------------
__global__ void attn_kernel(const float* __restrict__ q, const float* __restrict__ k,
                            const float* __restrict__ v, const float* __restrict__ sph,
                            float* __restrict__ o) {
    extern __shared__ float smf[];
    float* ks = smf;
    float* vs = smf + 128 * 36;
    float* ps = smf + 2 * 128 * 36;
    float* pacc = ks;
    float* mxred = ks + 4096;
    float* smred = ks + 4352;
    int head = blockIdx.x, b = blockIdx.y;
    int tid = threadIdx.x;
    int s = tid & 127, p = tid >> 7;
    int nodebase = (b * SEQ + s) * HID + head * 32;
    float qr[32];
#pragma unroll
    for (int d4 = 0; d4 < 8; d4++) {
        float4 tq = *(const float4*)&q[nodebase + d4 * 4];
        qr[d4 * 4] = tq.x; qr[d4 * 4 + 1] = tq.y; qr[d4 * 4 + 2] = tq.z; qr[d4 * 4 + 3] = tq.w;
        if (p == 0)
            *(float4*)&ks[s * 36 + d4 * 4] = *(const float4*)&k[nodebase + d4 * 4];
        else
            *(float4*)&vs[s * 36 + d4 * 4] = *(const float4*)&v[nodebase + d4 * 4];
    }
    __syncthreads();
    const float isd = 0.17677669529663687f;
    int t0 = p * 64;
    for (int t = t0; t < t0 + 64; t++) {
        float acc = 0.f;
#pragma unroll
        for (int d4 = 0; d4 < 8; d4++) {
            float4 kk = *(float4*)&ks[t * 36 + d4 * 4];
            acc += qr[d4 * 4] * kk.x + qr[d4 * 4 + 1] * kk.y +
                   qr[d4 * 4 + 2] * kk.z + qr[d4 * 4 + 3] * kk.w;
        }
        ps[s * 133 + t] = acc * isd;
    }
    __syncthreads();
    const float* sb = sph + b * SEQ * SEQ;
    for (int i = tid; i < SEQ * SEQ; i += 256) {
        int s2 = i >> 7, t2 = i & 127;
        ps[s2 * 133 + t2] *= sb[i];
    }
    __syncthreads();
    float mx = -1e30f;
    for (int t = t0; t < t0 + 64; t++) mx = fmaxf(mx, ps[s * 133 + t]);
    mxred[p * 128 + s] = mx;
    __syncthreads();
    float gmx = fmaxf(mxred[s], mxred[128 + s]);
    float sum = 0.f;
    for (int t = t0; t < t0 + 64; t++) {
        float e = __expf(ps[s * 133 + t] - gmx);
        ps[s * 133 + t] = e;
        sum += e;
    }
    smred[p * 128 + s] = sum;
    __syncthreads();
    float inv = 1.f / (smred[s] + smred[128 + s]);
    float acc[32];
#pragma unroll
    for (int d = 0; d < 32; d++) acc[d] = 0.f;
    for (int t = t0; t < t0 + 64; t++) {
        float pw = ps[s * 133 + t];
#pragma unroll
        for (int d4 = 0; d4 < 8; d4++) {
            float4 vvv = *(float4*)&vs[t * 36 + d4 * 4];
            acc[d4 * 4] += pw * vvv.x; acc[d4 * 4 + 1] += pw * vvv.y;
            acc[d4 * 4 + 2] += pw * vvv.z; acc[d4 * 4 + 3] += pw * vvv.w;
        }
    }
    if (p == 1) {
#pragma unroll
        for (int d = 0; d < 32; d++) pacc[d * 128 + s] = acc[d];
    }
    __syncthreads();
    if (p == 0) {
#pragma unroll
        for (int d4 = 0; d4 < 8; d4++) {
            float4 t4;
            t4.x = (acc[d4 * 4] + pacc[(d4 * 4) * 128 + s]) * inv;
            t4.y = (acc[d4 * 4 + 1] + pacc[(d4 * 4 + 1) * 128 + s]) * inv;
            t4.z = (acc[d4 * 4 + 2] + pacc[(d4 * 4 + 2) * 128 + s]) * inv;
            t4.w = (acc[d4 * 4 + 3] + pacc[(d4 * 4 + 3) * 128 + s]) * inv;
            *(float4*)&o[nodebase + d4 * 4] = t4;
        }
    }
}

// ---------------- mean pool + tiny MLP ----------------
__global__ void pool_kernel() {
    int b = blockIdx.x, c = threadIdx.x;
    float s = 0.f;
    for (int i = 0; i < SEQ; i++) s += g_h[(b * SEQ + i) * HID + c];
    g_pool[b * HID + c] = s * (1.f / 128.f);
}
__global__ void mlp_kernel(const float* __restrict__ in, const float* __restrict__ W,
                           const float* __restrict__ bias, float* __restrict__ out,
                           int K, int Ncol, int doRelu) {
    int r = blockIdx.x;
    __shared__ float xs[128];
    if ((int)threadIdx.x < K) xs[threadIdx.x] = in[r * K + threadIdx.x];
    __syncthreads();
    int c = threadIdx.x;
    if (c < Ncol) {
        float acc = bias[c];
        for (int k = 0; k < K; k++) acc += xs[k] * W[k * Ncol + c];
        if (doRelu) acc = fmaxf(acc, 0.f);
        out[r * Ncol + c] = acc;
    }
}

// ---------------- launch ----------------
extern "C" void kernel_launch(void* const* d_in, const int* in_sizes, int n_in,
                              void* d_out, int out_size) {
    const float* x        = (const float*)d_in[0];
    const float* pe       = (const float*)d_in[1];
    const float* edge_attr= (const float*)d_in[2];
    const float* sph      = (const float*)d_in[3];
    const float* node_w   = (const float*)d_in[4];
    const float* node_b   = (const float*)d_in[5];
    const float* pe_w     = (const float*)d_in[6];
    const float* pe_b     = (const float*)d_in[7];
    const float* Aw       = (const float*)d_in[8];
    const float* Ab       = (const float*)d_in[9];
    const float* Bw       = (const float*)d_in[10];
    const float* Bb       = (const float*)d_in[11];
    const float* Cw       = (const float*)d_in[12];
    const float* Cb       = (const float*)d_in[13];
    const float* Dw       = (const float*)d_in[14];
    const float* Db       = (const float*)d_in[15];
    const float* Ew       = (const float*)d_in[16];
    const float* Eb       = (const float*)d_in[17];
    const float* bnxg     = (const float*)d_in[18];
    const float* bnxb     = (const float*)d_in[19];
    const float* bneg     = (const float*)d_in[20];
    const float* bneb     = (const float*)d_in[21];
    const float* attw     = (const float*)d_in[22];
    const float* attb     = (const float*)d_in[23];
    const float* m1w      = (const float*)d_in[24];
    const float* m1b      = (const float*)d_in[25];
    const float* m2w      = (const float*)d_in[26];
    const float* m2b      = (const float*)d_in[27];
    const float* m3w      = (const float*)d_in[28];
    const float* m3b      = (const float*)d_in[29];
    const int*   ei       = (const int*)d_in[30];
    float* out = (float*)d_out;

    float *p_h, *p_eA, *p_eB, *p_eijA, *p_eijB, *p_Ax, *p_Bx, *p_Dx, *p_Ex, *p_num, *p_den;
    float *p_scN, *p_shN, *p_scE, *p_shE, *p_pool, *p_t1, *p_t2;
    unsigned* p_Wpack;
    cudaGetSymbolAddress((void**)&p_h,    g_h);
    cudaGetSymbolAddress((void**)&p_eA,   g_eA);
    cudaGetSymbolAddress((void**)&p_eB,   g_eB);
    cudaGetSymbolAddress((void**)&p_eijA, g_eijA);
    cudaGetSymbolAddress((void**)&p_eijB, g_eijB);
    cudaGetSymbolAddress((void**)&p_Ax,   g_Ax);
    cudaGetSymbolAddress((void**)&p_Bx,   g_Bx);
    cudaGetSymbolAddress((void**)&p_Dx,   g_Dx);
    cudaGetSymbolAddress((void**)&p_Ex,   g_Ex);
    cudaGetSymbolAddress((void**)&p_num,  g_num);
    cudaGetSymbolAddress((void**)&p_den,  g_den);
    cudaGetSymbolAddress((void**)&p_scN,  g_scN);
    cudaGetSymbolAddress((void**)&p_shN,  g_shN);
    cudaGetSymbolAddress((void**)&p_scE,  g_scE);
    cudaGetSymbolAddress((void**)&p_shE,  g_shE);
    cudaGetSymbolAddress((void**)&p_pool, g_pool);
    cudaGetSymbolAddress((void**)&p_t1,   g_t1);
    cudaGetSymbolAddress((void**)&p_t2,   g_t2);
    cudaGetSymbolAddress((void**)&p_Wpack, g_Wpack);

    float* eij_bufs[2] = { p_eijA, p_eijB };
    float* e_bufs[2]   = { p_eA, p_eB };

    const int* src = ei;
    const int* dst = ei + NE;
    const int ATTN_SMEM = (2 * 128 * 36 + 128 * 133) * 4;
    const int PLAIN_SMEM = OPW * 4;
    const int EDGE_SMEM = (OPW + 384) * 4;
    cudaFuncSetAttribute(attn_kernel, cudaFuncAttributeMaxDynamicSharedMemorySize, ATTN_SMEM);
    cudaFuncSetAttribute(gemm_tc, cudaFuncAttributeMaxDynamicSharedMemorySize, PLAIN_SMEM);
    cudaFuncSetAttribute(gemm_tc_edge, cudaFuncAttributeMaxDynamicSharedMemorySize, EDGE_SMEM);

    init_kernel<<<16, 256>>>();
    pack_w_kernel<<<24, 256>>>(Aw, Bw, Dw, Ew, Cw, attw);
    hist_kernel<<<NE / 256, 256>>>(dst);
    scan_kernel<<<1, 1024>>>();
    scatter_kernel<<<NE / 256, 256>>>(src, dst);
    input_proj_kernel<<<NND, 128>>>(x, pe, node_w, node_b, pe_w, pe_b);

    for (int l = 0; l < NL; l++) {
        dim3 g4(NND / 128, 4, 2);
        gemm_tc<<<g4, 256, PLAIN_SMEM>>>(p_h, nullptr, 0, 1,
            p_Wpack + (l * 5 + 0) * 16384, p_Wpack + (l * 5 + 1) * 16384,
            p_Wpack + (l * 5 + 2) * 16384, p_Wpack + (l * 5 + 3) * 16384,
            Ab + l * HID, Bb + l * HID, Db + l * HID, Eb + l * HID,
            p_Ax, p_Bx, p_Dx, p_Ex);
        const float* eA    = (l == 0) ? edge_attr : eij_bufs[(l - 1) & 1];
        float* eij_out     = eij_bufs[l & 1];
        const float* foldE = (l == 0) ? nullptr : ((l == 1) ? edge_attr : e_bufs[(l - 1) & 1]);
        float* fold_out    = e_bufs[l & 1];
        int permA = (l == 0) ? 1 : 0;
        int permF = (l == 1) ? 1 : 0;
        int last = (l == NL - 1);
        gemm_tc_edge<<<NE / 64, 256, EDGE_SMEM>>>(
            eA, foldE, fold_out, p_Wpack + (l * 5 + 4) * 16384, Cb + l * HID, eij_out,
            p_Dx, p_Ex, p_Bx, last ? 0 : 1, permA, permF,
            last ? 0 : 1, last ? 0 : 1);
        if (!last)
            bn_fin_kernel<<<1, 128>>>(0, 1.f / NE, bneg + l * HID, bneb + l * HID, p_scE, p_shE);
        node_hnew_stats_kernel<<<1024, 128>>>();
        bn_fin_kernel<<<1, 128>>>(256, 1.f / NND, bnxg + l * HID, bnxb + l * HID, p_scN, p_shN);
        dim3 g3(NND / 128, 3, 2);
        gemm_tc<<<g3, 256, PLAIN_SMEM>>>(p_Ax, p_h, 1, 0,
            p_Wpack + 20 * 16384, p_Wpack + 21 * 16384,
            p_Wpack + 22 * 16384, p_Wpack + 22 * 16384,
            attb + 0 * HID, attb + 1 * HID, attb + 2 * HID, attb + 2 * HID,
            p_den, p_Bx, p_Dx, p_Dx);
        dim3 ag(4, BATCH);
        attn_kernel<<<ag, 256, ATTN_SMEM>>>(p_den, p_Bx, p_Dx, sph, p_Ex);
        dim3 g1(NND / 128, 1, 2);
        gemm_tc<<<g1, 256, PLAIN_SMEM>>>(p_Ex, nullptr, 0, 0,
            p_Wpack + 23 * 16384, p_Wpack + 23 * 16384,
            p_Wpack + 23 * 16384, p_Wpack + 23 * 16384,
            attb + 3 * HID, attb + 3 * HID, attb + 3 * HID, attb + 3 * HID,
            p_h, p_h, p_h, p_h);
    }
    pool_kernel<<<BATCH, 128>>>();
    mlp_kernel<<<BATCH, 128>>>(p_pool, m1w, m1b, p_t1, 128, 64, 1);
    mlp_kernel<<<BATCH, 128>>>(p_t1, m2w, m2b, p_t2, 64, 32, 1);
    mlp_kernel<<<BATCH, 128>>>(p_t2, m3w, m3b, out, 32, 10, 0);
}